// round 1
// baseline (speedup 1.0000x reference)
#include <cuda_runtime.h>
#include <math.h>

#define BATCH 16
#define C 256
#define CQK 32
#define NT 256   /* 16x16 */
#define NS 1024  /* 32x32 */

// ---------------- scratch (static device memory; allowed) ----------------
__device__ float g_q_t[BATCH*NT*CQK];
__device__ float g_k_t[BATCH*NT*CQK];
__device__ float g_q_s[BATCH*NS*CQK];
__device__ float g_k_s[BATCH*NS*CQK];
__device__ float g_v_t[BATCH*C*NT];
__device__ float g_v_s[BATCH*C*NS];
__device__ float g_att_t[BATCH*NT*NT];
__device__ float g_att_s[(size_t)BATCH*NS*NS];
__device__ float g_Gt[BATCH*C*C];
__device__ float g_Gs[BATCH*C*C];
__device__ float g_M[BATCH*C*C];
__device__ float g_at[BATCH*C*NT];
__device__ float g_as[BATCH*C*NS];
__device__ float g_off_t[BATCH*27*NT];
__device__ float g_off_s[BATCH*27*NS];
__device__ float g_col_t[(size_t)BATCH*C*9*NT];
__device__ float g_col_s[(size_t)BATCH*C*9*NS];

// ---------------- 1x1 conv producing (b, n, 32) layout for q/k ----------------
// grid: (N/32, B), block 256.  thread: nl = tid%32 (pixel), og = tid/32 (8 groups of 4 outputs)
__global__ void qk_conv(const float* __restrict__ x, const float* __restrict__ W,
                        const float* __restrict__ bias, float* __restrict__ out, int N)
{
    int b  = blockIdx.y;
    int n0 = blockIdx.x * 32;
    int nl = threadIdx.x & 31;
    int og = threadIdx.x >> 5;
    __shared__ float sx[32][33];
    __shared__ float sw[32][32];
    float acc[4] = {0.f, 0.f, 0.f, 0.f};
    for (int c0 = 0; c0 < C; c0 += 32) {
        #pragma unroll
        for (int i = 0; i < 4; i++) {
            sx[og*4+i][nl] = x[((long)b*C + c0 + og*4+i)*N + n0 + nl];
            sw[og*4+i][nl] = W[(og*4+i)*C + c0 + nl];
        }
        __syncthreads();
        #pragma unroll
        for (int cc = 0; cc < 32; cc++) {
            float xv = sx[cc][nl];
            #pragma unroll
            for (int i = 0; i < 4; i++) acc[i] += xv * sw[og*4+i][cc];
        }
        __syncthreads();
    }
    #pragma unroll
    for (int i = 0; i < 4; i++) {
        int o = og*4 + i;
        out[((long)b*N + n0 + nl)*CQK + o] = acc[i] + bias[o];
    }
}

// ---------------- generic tiled GEMM: C[m,n] (+)= sum_k A[m,k]*B[k,n] (+bias[m]) ----------------
// BT=true: B is stored as (N x K) row-major and used transposed (for gram f f^T).
// tile 64x64x16, 256 threads, 4x4 per thread. All problem dims here are multiples of 64/16.
template<bool BT>
__global__ void gemm64(const float* __restrict__ A, const float* __restrict__ B,
                       float* __restrict__ Cc, int M, int N, int K,
                       long sA, long sB, long sC,
                       const float* __restrict__ bias, int accumulate)
{
    const float* Ab = A + (long)blockIdx.z * sA;
    const float* Bb = B + (long)blockIdx.z * sB;
    float* Cb = Cc + (long)blockIdx.z * sC;
    __shared__ float As[16][64];
    __shared__ float Bs[16][64];
    int tid = threadIdx.x;
    int tx = tid & 15, ty = tid >> 4;
    int row0 = blockIdx.y * 64, col0 = blockIdx.x * 64;
    float acc[4][4] = {};
    for (int k0 = 0; k0 < K; k0 += 16) {
        #pragma unroll
        for (int l = tid; l < 1024; l += 256) {
            int i = l >> 4, j = l & 15;
            As[j][i] = Ab[(long)(row0 + i)*K + k0 + j];
        }
        if (!BT) {
            #pragma unroll
            for (int l = tid; l < 1024; l += 256) {
                int j = l >> 6, i = l & 63;
                Bs[j][i] = Bb[(long)(k0 + j)*N + col0 + i];
            }
        } else {
            #pragma unroll
            for (int l = tid; l < 1024; l += 256) {
                int i = l >> 4, j = l & 15;
                Bs[j][i] = Bb[(long)(col0 + i)*K + k0 + j];
            }
        }
        __syncthreads();
        #pragma unroll
        for (int kk = 0; kk < 16; kk++) {
            float4 av = *(const float4*)&As[kk][ty*4];
            float4 bv = *(const float4*)&Bs[kk][tx*4];
            float a0[4] = {av.x, av.y, av.z, av.w};
            float b0[4] = {bv.x, bv.y, bv.z, bv.w};
            #pragma unroll
            for (int i = 0; i < 4; i++)
                #pragma unroll
                for (int j = 0; j < 4; j++) acc[i][j] += a0[i] * b0[j];
        }
        __syncthreads();
    }
    #pragma unroll
    for (int i = 0; i < 4; i++) {
        int r = row0 + ty*4 + i;
        float bv = bias ? bias[r] : 0.f;
        #pragma unroll
        for (int j = 0; j < 4; j++) {
            int cidx = col0 + tx*4 + j;
            long idx = (long)r*N + cidx;
            float v = acc[i][j] + bv;
            if (accumulate) v += Cb[idx];
            Cb[idx] = v;
        }
    }
}

// ---------------- spatial attention: logits (dot over 32) + softmax over BATCH axis ----------------
// grid: (N/16, N/16), block 256 (16x16 nm pairs). q,k layout (b, n, 32); att (b, n, m).
__global__ void spatial_att(const float* __restrict__ q, const float* __restrict__ k,
                            float* __restrict__ att, int N)
{
    int n0 = blockIdx.y * 16, m0 = blockIdx.x * 16;
    int tn = threadIdx.x >> 4, tm = threadIdx.x & 15;
    __shared__ float sq[16][33], sk[16][33];
    float logit[BATCH];
    for (int b = 0; b < BATCH; b++) {
        int i = threadIdx.x >> 5, c = threadIdx.x & 31;
        sq[i][c]     = q[((long)b*N + n0 + i)*CQK + c];
        sq[i + 8][c] = q[((long)b*N + n0 + i + 8)*CQK + c];
        sk[i][c]     = k[((long)b*N + m0 + i)*CQK + c];
        sk[i + 8][c] = k[((long)b*N + m0 + i + 8)*CQK + c];
        __syncthreads();
        float acc = 0.f;
        #pragma unroll
        for (int c2 = 0; c2 < 32; c2++) acc += sq[tn][c2] * sk[tm][c2];
        logit[b] = acc;
        __syncthreads();
    }
    float mx = logit[0];
    #pragma unroll
    for (int b = 1; b < BATCH; b++) mx = fmaxf(mx, logit[b]);
    float s = 0.f;
    #pragma unroll
    for (int b = 0; b < BATCH; b++) { logit[b] = expf(logit[b] - mx); s += logit[b]; }
    float inv = 1.f / s;
    #pragma unroll
    for (int b = 0; b < BATCH; b++)
        att[(long)b*N*N + (long)(n0 + tn)*N + m0 + tm] = logit[b] * inv;
}

// ---------------- column softmax of gram (over c for each (b,d)), optionally accumulating ----------------
// grid: (C/32, B), block 256 = 8 c-groups x 32 d-lanes.
__global__ void softmax_col_add(const float* __restrict__ G, float* __restrict__ out, int accumulate)
{
    int b = blockIdx.y;
    long base = (long)b * C * C;
    int lane = threadIdx.x & 31;
    int cg = threadIdx.x >> 5;
    int d = blockIdx.x * 32 + lane;
    float vals[32];
    float mx = -1e30f;
    #pragma unroll
    for (int i = 0; i < 32; i++) {
        vals[i] = G[base + (long)(cg*32 + i)*C + d];
        mx = fmaxf(mx, vals[i]);
    }
    __shared__ float red[8][32];
    red[cg][lane] = mx;
    __syncthreads();
    if (cg == 0) {
        float m = red[0][lane];
        #pragma unroll
        for (int j = 1; j < 8; j++) m = fmaxf(m, red[j][lane]);
        red[0][lane] = m;
    }
    __syncthreads();
    mx = red[0][lane];
    __syncthreads();
    float s = 0.f;
    #pragma unroll
    for (int i = 0; i < 32; i++) { vals[i] = expf(vals[i] - mx); s += vals[i]; }
    red[cg][lane] = s;
    __syncthreads();
    if (cg == 0) {
        float m = 0.f;
        #pragma unroll
        for (int j = 1; j < 8; j++) m += red[j][lane];
        red[0][lane] += m;
    }
    __syncthreads();
    float inv = 1.f / red[0][lane];
    #pragma unroll
    for (int i = 0; i < 32; i++) {
        long idx = base + (long)(cg*32 + i)*C + d;
        float v = vals[i] * inv;
        if (accumulate) v += out[idx];
        out[idx] = v;
    }
}

__global__ void add_inplace(float* __restrict__ dst, const float* __restrict__ src, int n)
{
    int i = blockIdx.x * 256 + threadIdx.x;
    if (i < n) dst[i] += src[i];
}

// ---------------- 3x3 conv, 27 output channels (offset/mask conv), SAME zero pad ----------------
// grid: (H, B), block 256. thread: w = tid%W, og = tid/W; each group handles oc = og + g*(256/W).
__global__ void conv3x3_off(const float* __restrict__ x, const float* __restrict__ w,
                            const float* __restrict__ bias, float* __restrict__ out,
                            int H, int Wd)
{
    int b = blockIdx.y, h = blockIdx.x;
    int N = H * Wd;
    int wl = threadIdx.x % Wd;
    int og = threadIdx.x / Wd;
    int OCG = 256 / Wd;
    __shared__ float sx[16][3][32];
    __shared__ float sw[27][16][9];
    int ocs[4]; bool on[4];
    #pragma unroll
    for (int g = 0; g < 4; g++) { ocs[g] = og + g*OCG; on[g] = (ocs[g] < 27); }
    float acc[4] = {0.f, 0.f, 0.f, 0.f};
    for (int c0 = 0; c0 < C; c0 += 16) {
        for (int l = threadIdx.x; l < 27*16*9; l += 256) {
            int oc = l / 144, rem = l % 144, cc = rem / 9, p = rem % 9;
            sw[oc][cc][p] = w[((long)oc*C + c0 + cc)*9 + p];
        }
        for (int l = threadIdx.x; l < 16*3*Wd; l += 256) {
            int cc = l / (3*Wd), r = (l / Wd) % 3, ww = l % Wd;
            int hh = h + r - 1;
            float v = 0.f;
            if (hh >= 0 && hh < H) v = x[((long)b*C + c0 + cc)*N + hh*Wd + ww];
            sx[cc][r][ww] = v;
        }
        __syncthreads();
        for (int cc = 0; cc < 16; cc++) {
            #pragma unroll
            for (int p = 0; p < 9; p++) {
                int dy = p / 3, dx = p % 3;
                int wloc = wl + dx - 1;
                float xv = (wloc >= 0 && wloc < Wd) ? sx[cc][dy][wloc] : 0.f;
                #pragma unroll
                for (int g = 0; g < 4; g++)
                    if (on[g]) acc[g] += xv * sw[ocs[g]][cc][p];
            }
        }
        __syncthreads();
    }
    #pragma unroll
    for (int g = 0; g < 4; g++)
        if (on[g]) out[((long)b*27 + ocs[g])*N + h*Wd + wl] = acc[g] + bias[ocs[g]];
}

// ---------------- deformable sampling -> im2col: col[b, c*9+k, hw] ----------------
// grid: (N/64, 9, B), block 256 (4 c-lanes x 64 hw).
__global__ void dcn_sample(const float* __restrict__ x, const float* __restrict__ off,
                           float* __restrict__ col, int H, int Wd)
{
    int b = blockIdx.z, k = blockIdx.y;
    int N = H * Wd;
    int hw0 = blockIdx.x * 64;
    __shared__ float s_w[4][64];
    __shared__ int s_a[4][64];
    int tid = threadIdx.x;
    if (tid < 64) {
        int hw = hw0 + tid;
        int h = hw / Wd, ww = hw % Wd;
        long ob = (long)b * 27 * N;
        float oy = off[ob + (2*k)*N + hw];
        float ox = off[ob + (2*k + 1)*N + hw];
        float mz = off[ob + (18 + k)*N + hw];
        float mk = 1.f / (1.f + expf(-mz));
        float y  = (float)(h - 1 + k/3) + oy;
        float xx = (float)(ww - 1 + k%3) + ox;
        float y0f = floorf(y), x0f = floorf(xx);
        float wy = y - y0f, wx = xx - x0f;
        int y0 = (int)y0f, x0 = (int)x0f;
        #pragma unroll
        for (int c2 = 0; c2 < 4; c2++) {
            int dy = c2 >> 1, dx = c2 & 1;
            int yy = y0 + dy, xc = x0 + dx;
            bool valid = (yy >= 0 && yy < H && xc >= 0 && xc < Wd);
            float wgt = (dy ? wy : 1.f - wy) * (dx ? wx : 1.f - wx) * mk;
            int yyc = min(max(yy, 0), H - 1), xcc = min(max(xc, 0), Wd - 1);
            s_w[c2][tid] = valid ? wgt : 0.f;
            s_a[c2][tid] = yyc*Wd + xcc;
        }
    }
    __syncthreads();
    int hwi = tid & 63;
    int cl = tid >> 6;
    float w0 = s_w[0][hwi], w1 = s_w[1][hwi], w2 = s_w[2][hwi], w3 = s_w[3][hwi];
    int a0 = s_a[0][hwi], a1 = s_a[1][hwi], a2 = s_a[2][hwi], a3 = s_a[3][hwi];
    for (int c = cl; c < C; c += 4) {
        const float* xp = x + ((long)b*C + c)*N;
        float v = w0*xp[a0] + w1*xp[a1] + w2*xp[a2] + w3*xp[a3];
        col[((long)b*C*9 + c*9 + k)*N + hw0 + hwi] = v;
    }
}

// ---------------- launch ----------------
extern "C" void kernel_launch(void* const* d_in, const int* in_sizes, int n_in,
                              void* d_out, int out_size)
{
    (void)in_sizes; (void)n_in; (void)out_size;
    const float* t     = (const float*)d_in[0];
    const float* s     = (const float*)d_in[1];
    const float* tq_w  = (const float*)d_in[2];
    const float* tq_b  = (const float*)d_in[3];
    const float* tk_w  = (const float*)d_in[4];
    const float* tk_b  = (const float*)d_in[5];
    const float* tv_w  = (const float*)d_in[6];
    const float* tv_b  = (const float*)d_in[7];
    const float* sq_w  = (const float*)d_in[8];
    const float* sq_b  = (const float*)d_in[9];
    const float* sk_w  = (const float*)d_in[10];
    const float* sk_b  = (const float*)d_in[11];
    const float* sv_w  = (const float*)d_in[12];
    const float* sv_b  = (const float*)d_in[13];
    const float* t_off_w = (const float*)d_in[14];
    const float* t_off_b = (const float*)d_in[15];
    const float* t_dcn_w = (const float*)d_in[16];
    const float* t_dcn_b = (const float*)d_in[17];
    const float* s_off_w = (const float*)d_in[18];
    const float* s_off_b = (const float*)d_in[19];
    const float* s_dcn_w = (const float*)d_in[20];
    const float* s_dcn_b = (const float*)d_in[21];
    float* out_t = (float*)d_out;
    float* out_s = out_t + (long)BATCH*C*NT;

    float *q_t, *k_t, *q_s, *k_s, *v_t, *v_s, *att_t, *att_s;
    float *Gt, *Gs, *Mm, *at_, *as_, *off_t, *off_s, *col_t, *col_s;
    cudaGetSymbolAddress((void**)&q_t,  g_q_t);
    cudaGetSymbolAddress((void**)&k_t,  g_k_t);
    cudaGetSymbolAddress((void**)&q_s,  g_q_s);
    cudaGetSymbolAddress((void**)&k_s,  g_k_s);
    cudaGetSymbolAddress((void**)&v_t,  g_v_t);
    cudaGetSymbolAddress((void**)&v_s,  g_v_s);
    cudaGetSymbolAddress((void**)&att_t, g_att_t);
    cudaGetSymbolAddress((void**)&att_s, g_att_s);
    cudaGetSymbolAddress((void**)&Gt,   g_Gt);
    cudaGetSymbolAddress((void**)&Gs,   g_Gs);
    cudaGetSymbolAddress((void**)&Mm,   g_M);
    cudaGetSymbolAddress((void**)&at_,  g_at);
    cudaGetSymbolAddress((void**)&as_,  g_as);
    cudaGetSymbolAddress((void**)&off_t, g_off_t);
    cudaGetSymbolAddress((void**)&off_s, g_off_s);
    cudaGetSymbolAddress((void**)&col_t, g_col_t);
    cudaGetSymbolAddress((void**)&col_s, g_col_s);

    // 1) q,k (layout (b,n,32)) and v (layout (b,c,n)) projections
    qk_conv<<<dim3(NT/32, BATCH), 256>>>(t, tq_w, tq_b, q_t, NT);
    qk_conv<<<dim3(NT/32, BATCH), 256>>>(t, tk_w, tk_b, k_t, NT);
    qk_conv<<<dim3(NS/32, BATCH), 256>>>(s, sq_w, sq_b, q_s, NS);
    qk_conv<<<dim3(NS/32, BATCH), 256>>>(s, sk_w, sk_b, k_s, NS);
    gemm64<false><<<dim3(NT/64, C/64, BATCH), 256>>>(tv_w, t, v_t, C, NT, C, 0, (long)C*NT, (long)C*NT, tv_b, 0);
    gemm64<false><<<dim3(NS/64, C/64, BATCH), 256>>>(sv_w, s, v_s, C, NS, C, 0, (long)C*NS, (long)C*NS, sv_b, 0);

    // 2) spatial attention maps (softmax over batch axis!)
    spatial_att<<<dim3(NT/16, NT/16), 256>>>(q_t, k_t, att_t, NT);
    spatial_att<<<dim3(NS/16, NS/16), 256>>>(q_s, k_s, att_s, NS);

    // 3) spatial out = v @ att  -> g_at / g_as
    gemm64<false><<<dim3(NT/64, C/64, BATCH), 256>>>(v_t, att_t, at_, C, NT, NT, (long)C*NT, (long)NT*NT, (long)C*NT, nullptr, 0);
    gemm64<false><<<dim3(NS/64, C/64, BATCH), 256>>>(v_s, att_s, as_, C, NS, NS, (long)C*NS, (long)NS*NS, (long)C*NS, nullptr, 0);

    // 4) grams G = f f^T, column-softmax, combine M = A_t + A_s
    gemm64<true><<<dim3(C/64, C/64, BATCH), 256>>>(t, t, Gt, C, C, NT, (long)C*NT, (long)C*NT, (long)C*C, nullptr, 0);
    gemm64<true><<<dim3(C/64, C/64, BATCH), 256>>>(s, s, Gs, C, C, NS, (long)C*NS, (long)C*NS, (long)C*C, nullptr, 0);
    softmax_col_add<<<dim3(C/32, BATCH), 256>>>(Gt, Mm, 0);
    softmax_col_add<<<dim3(C/32, BATCH), 256>>>(Gs, Mm, 1);

    // 5) residual + channel/cross apply: at = t + spatial_t + M@t ; asr = s + spatial_s + M@s
    add_inplace<<<(BATCH*C*NT + 255)/256, 256>>>(at_, t, BATCH*C*NT);
    add_inplace<<<(BATCH*C*NS + 255)/256, 256>>>(as_, s, BATCH*C*NS);
    gemm64<false><<<dim3(NT/64, C/64, BATCH), 256>>>(Mm, t, at_, C, NT, C, (long)C*C, (long)C*NT, (long)C*NT, nullptr, 1);
    gemm64<false><<<dim3(NS/64, C/64, BATCH), 256>>>(Mm, s, as_, C, NS, C, (long)C*C, (long)C*NS, (long)C*NS, nullptr, 1);

    // 6) offset/mask conv (27 channels)
    conv3x3_off<<<dim3(16, BATCH), 256>>>(at_, t_off_w, t_off_b, off_t, 16, 16);
    conv3x3_off<<<dim3(32, BATCH), 256>>>(as_, s_off_w, s_off_b, off_s, 32, 32);

    // 7) deformable bilinear sampling -> im2col
    dcn_sample<<<dim3(NT/64, 9, BATCH), 256>>>(at_, off_t, col_t, 16, 16);
    dcn_sample<<<dim3(NS/64, 9, BATCH), 256>>>(as_, off_s, col_s, 32, 32);

    // 8) dcn main GEMM: out = W(256x2304) @ col + bias  -> final outputs
    gemm64<false><<<dim3(NT/64, C/64, BATCH), 256>>>(t_dcn_w, col_t, out_t, C, NT, C*9, 0, (long)C*9*NT, (long)C*NT, t_dcn_b, 0);
    gemm64<false><<<dim3(NS/64, C/64, BATCH), 256>>>(s_dcn_w, col_s, out_s, C, NS, C*9, 0, (long)C*9*NS, (long)C*NS, s_dcn_b, 0);
}

// round 2
// speedup vs baseline: 1.4759x; 1.4759x over previous
#include <cuda_runtime.h>
#include <math.h>

#define BATCH 16
#define C 256
#define CQK 32
#define NT 256   /* 16x16 */
#define NS 1024  /* 32x32 */

// ---------------- scratch (static device memory; allowed) ----------------
__device__ float g_q_t[BATCH*NT*CQK];
__device__ float g_k_t[BATCH*NT*CQK];
__device__ float g_q_s[BATCH*NS*CQK];
__device__ float g_k_s[BATCH*NS*CQK];
__device__ float g_v_t[BATCH*C*NT];
__device__ float g_v_s[BATCH*C*NS];
__device__ float g_att_t[BATCH*NT*NT];
__device__ float g_att_s[(size_t)BATCH*NS*NS];
__device__ float g_Gt[BATCH*C*C];
__device__ float g_Gs[BATCH*C*C];
__device__ float g_M[BATCH*C*C];
__device__ float g_at[BATCH*C*NT];
__device__ float g_as[BATCH*C*NS];
__device__ float g_off_t[BATCH*27*NT];
__device__ float g_off_s[BATCH*27*NS];
__device__ float g_col_t[(size_t)BATCH*C*9*NT];
__device__ float g_col_s[(size_t)BATCH*C*9*NS];

// ---------------- 1x1 conv producing (b, n, 32) layout for q/k ----------------
__global__ void qk_conv(const float* __restrict__ x, const float* __restrict__ W,
                        const float* __restrict__ bias, float* __restrict__ out, int N)
{
    int b  = blockIdx.y;
    int n0 = blockIdx.x * 32;
    int nl = threadIdx.x & 31;
    int og = threadIdx.x >> 5;
    __shared__ float sx[32][33];
    __shared__ float sw[32][32];
    float acc[4] = {0.f, 0.f, 0.f, 0.f};
    for (int c0 = 0; c0 < C; c0 += 32) {
        #pragma unroll
        for (int i = 0; i < 4; i++) {
            sx[og*4+i][nl] = x[((long)b*C + c0 + og*4+i)*N + n0 + nl];
            sw[og*4+i][nl] = W[(og*4+i)*C + c0 + nl];
        }
        __syncthreads();
        #pragma unroll
        for (int cc = 0; cc < 32; cc++) {
            float xv = sx[cc][nl];
            #pragma unroll
            for (int i = 0; i < 4; i++) acc[i] += xv * sw[og*4+i][cc];
        }
        __syncthreads();
    }
    #pragma unroll
    for (int i = 0; i < 4; i++) {
        int o = og*4 + i;
        out[((long)b*N + n0 + nl)*CQK + o] = acc[i] + bias[o];
    }
}

// ---------------- big tiled GEMM: C[m,n] (+)= sum_k A[m,k]*B[k,n] (+bias[m]) (+residual) --------
// BM x BN x 8 tile, 256 threads, (BM/16 x BN/16) per thread, double-buffered smem.
// BT=true: B stored (N x K) row-major, used transposed.
template<int BM, int BN, bool BT>
__global__ __launch_bounds__(256, 2)
void gemm_big(const float* __restrict__ A, const float* __restrict__ B,
              float* __restrict__ Cc, int M, int N, int K,
              long sA, long sB, long sC,
              const float* __restrict__ bias,
              const float* __restrict__ residual, int accumulate)
{
    constexpr int TM = BM/16, TN = BN/16;
    constexpr int AL2 = (BM*4)/256;            // float2 A loads/thread
    constexpr int BL4 = (BN*2 + 255)/256;      // float4 B loads/thread (non-BT)
    constexpr int BL2 = (BN*4 + 255)/256;      // float2 B loads/thread (BT)
    constexpr bool BGUARD4 = (BN*2 < 256);
    constexpr bool BGUARD2 = (BN*4 < 256);

    const float* Ab = A + (long)blockIdx.z*sA;
    const float* Bb = B + (long)blockIdx.z*sB;
    float* Cb = Cc + (long)blockIdx.z*sC;
    const float* Rb = residual ? residual + (long)blockIdx.z*sC : nullptr;

    __shared__ float As[2][8][BM+4];
    __shared__ float Bs[2][8][BN+4];

    int tid = threadIdx.x;
    int tx = tid & 15, ty = tid >> 4;
    int row0 = blockIdx.y * BM, col0 = blockIdx.x * BN;

    float acc[TM][TN];
    #pragma unroll
    for (int i = 0; i < TM; i++)
        #pragma unroll
        for (int j = 0; j < TN; j++) acc[i][j] = 0.f;

    float2 ra[AL2];
    float4 rbv[(BT ? 1 : BL4)];
    float2 rbt[(BT ? BL2 : 1)];

    auto fetchA = [&](int k0) {
        #pragma unroll
        for (int i = 0; i < AL2; i++) {
            int l = tid + i*256;
            int m = l >> 2, k = (l & 3) * 2;
            ra[i] = *(const float2*)&Ab[(long)(row0+m)*K + k0 + k];
        }
    };
    auto storeA = [&](int buf) {
        #pragma unroll
        for (int i = 0; i < AL2; i++) {
            int l = tid + i*256;
            int m = l >> 2, k = (l & 3) * 2;
            As[buf][k][m]   = ra[i].x;
            As[buf][k+1][m] = ra[i].y;
        }
    };
    auto fetchB = [&](int k0) {
        if (!BT) {
            #pragma unroll
            for (int i = 0; i < BL4; i++) {
                int l = tid + i*256;
                if (!BGUARD4 || l < BN*2) {
                    int k = l / (BN/4), n = (l % (BN/4)) * 4;
                    rbv[i] = *(const float4*)&Bb[(long)(k0+k)*N + col0 + n];
                }
            }
        } else {
            #pragma unroll
            for (int i = 0; i < BL2; i++) {
                int l = tid + i*256;
                if (!BGUARD2 || l < BN*4) {
                    int n = l >> 2, k = (l & 3) * 2;
                    rbt[i] = *(const float2*)&Bb[(long)(col0+n)*K + k0 + k];
                }
            }
        }
    };
    auto storeB = [&](int buf) {
        if (!BT) {
            #pragma unroll
            for (int i = 0; i < BL4; i++) {
                int l = tid + i*256;
                if (!BGUARD4 || l < BN*2) {
                    int k = l / (BN/4), n = (l % (BN/4)) * 4;
                    *(float4*)&Bs[buf][k][n] = rbv[i];
                }
            }
        } else {
            #pragma unroll
            for (int i = 0; i < BL2; i++) {
                int l = tid + i*256;
                if (!BGUARD2 || l < BN*4) {
                    int n = l >> 2, k = (l & 3) * 2;
                    Bs[buf][k][n]   = rbt[i].x;
                    Bs[buf][k+1][n] = rbt[i].y;
                }
            }
        }
    };
    auto compute = [&](int buf) {
        #pragma unroll
        for (int kk = 0; kk < 8; kk++) {
            float a[TM], b[TN];
            #pragma unroll
            for (int i = 0; i < TM; i += 4)
                *(float4*)&a[i] = *(const float4*)&As[buf][kk][ty*TM + i];
            #pragma unroll
            for (int j = 0; j < TN; j += 4)
                *(float4*)&b[j] = *(const float4*)&Bs[buf][kk][tx*TN + j];
            #pragma unroll
            for (int i = 0; i < TM; i++)
                #pragma unroll
                for (int j = 0; j < TN; j++)
                    acc[i][j] += a[i] * b[j];
        }
    };

    fetchA(0); fetchB(0);
    storeA(0); storeB(0);
    __syncthreads();
    int buf = 0;
    for (int k0 = 0; k0 < K; k0 += 8) {
        bool has_next = (k0 + 8 < K);
        if (has_next) { fetchA(k0 + 8); fetchB(k0 + 8); }
        compute(buf);
        if (has_next) {
            storeA(buf ^ 1); storeB(buf ^ 1);
            __syncthreads();
            buf ^= 1;
        }
    }

    #pragma unroll
    for (int i = 0; i < TM; i++) {
        int r = row0 + ty*TM + i;
        float bv = bias ? bias[r] : 0.f;
        #pragma unroll
        for (int j = 0; j < TN; j += 4) {
            long idx = (long)r*N + col0 + tx*TN + j;
            float4 v = *(float4*)&acc[i][j];
            v.x += bv; v.y += bv; v.z += bv; v.w += bv;
            if (accumulate) {
                float4 o = *(const float4*)&Cb[idx];
                v.x += o.x; v.y += o.y; v.z += o.z; v.w += o.w;
            }
            if (Rb) {
                float4 o = *(const float4*)&Rb[idx];
                v.x += o.x; v.y += o.y; v.z += o.z; v.w += o.w;
            }
            *(float4*)&Cb[idx] = v;
        }
    }
}

// ---------------- spatial attention: logits (dot over 32) + softmax over BATCH axis ----------------
__global__ void spatial_att(const float* __restrict__ q, const float* __restrict__ k,
                            float* __restrict__ att, int N)
{
    int n0 = blockIdx.y * 16, m0 = blockIdx.x * 16;
    int tn = threadIdx.x >> 4, tm = threadIdx.x & 15;
    __shared__ float sq[16][33], sk[16][33];
    float logit[BATCH];
    for (int b = 0; b < BATCH; b++) {
        int i = threadIdx.x >> 5, c = threadIdx.x & 31;
        sq[i][c]     = q[((long)b*N + n0 + i)*CQK + c];
        sq[i + 8][c] = q[((long)b*N + n0 + i + 8)*CQK + c];
        sk[i][c]     = k[((long)b*N + m0 + i)*CQK + c];
        sk[i + 8][c] = k[((long)b*N + m0 + i + 8)*CQK + c];
        __syncthreads();
        float acc = 0.f;
        #pragma unroll
        for (int c2 = 0; c2 < 32; c2++) acc += sq[tn][c2] * sk[tm][c2];
        logit[b] = acc;
        __syncthreads();
    }
    float mx = logit[0];
    #pragma unroll
    for (int b = 1; b < BATCH; b++) mx = fmaxf(mx, logit[b]);
    float s = 0.f;
    #pragma unroll
    for (int b = 0; b < BATCH; b++) { logit[b] = expf(logit[b] - mx); s += logit[b]; }
    float inv = 1.f / s;
    #pragma unroll
    for (int b = 0; b < BATCH; b++)
        att[(long)b*N*N + (long)(n0 + tn)*N + m0 + tm] = logit[b] * inv;
}

// ---------------- column softmax of gram (over c for each (b,d)), optionally accumulating ----------------
__global__ void softmax_col_add(const float* __restrict__ G, float* __restrict__ out, int accumulate)
{
    int b = blockIdx.y;
    long base = (long)b * C * C;
    int lane = threadIdx.x & 31;
    int cg = threadIdx.x >> 5;
    int d = blockIdx.x * 32 + lane;
    float vals[32];
    float mx = -1e30f;
    #pragma unroll
    for (int i = 0; i < 32; i++) {
        vals[i] = G[base + (long)(cg*32 + i)*C + d];
        mx = fmaxf(mx, vals[i]);
    }
    __shared__ float red[8][32];
    red[cg][lane] = mx;
    __syncthreads();
    if (cg == 0) {
        float m = red[0][lane];
        #pragma unroll
        for (int j = 1; j < 8; j++) m = fmaxf(m, red[j][lane]);
        red[0][lane] = m;
    }
    __syncthreads();
    mx = red[0][lane];
    __syncthreads();
    float s = 0.f;
    #pragma unroll
    for (int i = 0; i < 32; i++) { vals[i] = expf(vals[i] - mx); s += vals[i]; }
    red[cg][lane] = s;
    __syncthreads();
    if (cg == 0) {
        float m = 0.f;
        #pragma unroll
        for (int j = 1; j < 8; j++) m += red[j][lane];
        red[0][lane] += m;
    }
    __syncthreads();
    float inv = 1.f / red[0][lane];
    #pragma unroll
    for (int i = 0; i < 32; i++) {
        long idx = base + (long)(cg*32 + i)*C + d;
        float v = vals[i] * inv;
        if (accumulate) v += out[idx];
        out[idx] = v;
    }
}

// ---------------- 3x3 conv, 27 output channels (offset/mask conv), SAME zero pad ----------------
__global__ void conv3x3_off(const float* __restrict__ x, const float* __restrict__ w,
                            const float* __restrict__ bias, float* __restrict__ out,
                            int H, int Wd)
{
    int b = blockIdx.y, h = blockIdx.x;
    int N = H * Wd;
    int wl = threadIdx.x % Wd;
    int og = threadIdx.x / Wd;
    int OCG = 256 / Wd;
    __shared__ float sx[16][3][32];
    __shared__ float sw[27][16][9];
    int ocs[4]; bool on[4];
    #pragma unroll
    for (int g = 0; g < 4; g++) { ocs[g] = og + g*OCG; on[g] = (ocs[g] < 27); }
    float acc[4] = {0.f, 0.f, 0.f, 0.f};
    for (int c0 = 0; c0 < C; c0 += 16) {
        for (int l = threadIdx.x; l < 27*16*9; l += 256) {
            int oc = l / 144, rem = l % 144, cc = rem / 9, p = rem % 9;
            sw[oc][cc][p] = w[((long)oc*C + c0 + cc)*9 + p];
        }
        for (int l = threadIdx.x; l < 16*3*Wd; l += 256) {
            int cc = l / (3*Wd), r = (l / Wd) % 3, ww = l % Wd;
            int hh = h + r - 1;
            float v = 0.f;
            if (hh >= 0 && hh < H) v = x[((long)b*C + c0 + cc)*N + hh*Wd + ww];
            sx[cc][r][ww] = v;
        }
        __syncthreads();
        for (int cc = 0; cc < 16; cc++) {
            #pragma unroll
            for (int p = 0; p < 9; p++) {
                int dy = p / 3, dx = p % 3;
                int wloc = wl + dx - 1;
                float xv = (wloc >= 0 && wloc < Wd) ? sx[cc][dy][wloc] : 0.f;
                #pragma unroll
                for (int g = 0; g < 4; g++)
                    if (on[g]) acc[g] += xv * sw[ocs[g]][cc][p];
            }
        }
        __syncthreads();
    }
    #pragma unroll
    for (int g = 0; g < 4; g++)
        if (on[g]) out[((long)b*27 + ocs[g])*N + h*Wd + wl] = acc[g] + bias[ocs[g]];
}

// ---------------- deformable sampling -> im2col: col[b, c*9+k, hw] ----------------
__global__ void dcn_sample(const float* __restrict__ x, const float* __restrict__ off,
                           float* __restrict__ col, int H, int Wd)
{
    int b = blockIdx.z, k = blockIdx.y;
    int N = H * Wd;
    int hw0 = blockIdx.x * 64;
    __shared__ float s_w[4][64];
    __shared__ int s_a[4][64];
    int tid = threadIdx.x;
    if (tid < 64) {
        int hw = hw0 + tid;
        int h = hw / Wd, ww = hw % Wd;
        long ob = (long)b * 27 * N;
        float oy = off[ob + (2*k)*N + hw];
        float ox = off[ob + (2*k + 1)*N + hw];
        float mz = off[ob + (18 + k)*N + hw];
        float mk = 1.f / (1.f + expf(-mz));
        float y  = (float)(h - 1 + k/3) + oy;
        float xx = (float)(ww - 1 + k%3) + ox;
        float y0f = floorf(y), x0f = floorf(xx);
        float wy = y - y0f, wx = xx - x0f;
        int y0 = (int)y0f, x0 = (int)x0f;
        #pragma unroll
        for (int c2 = 0; c2 < 4; c2++) {
            int dy = c2 >> 1, dx = c2 & 1;
            int yy = y0 + dy, xc = x0 + dx;
            bool valid = (yy >= 0 && yy < H && xc >= 0 && xc < Wd);
            float wgt = (dy ? wy : 1.f - wy) * (dx ? wx : 1.f - wx) * mk;
            int yyc = min(max(yy, 0), H - 1), xcc = min(max(xc, 0), Wd - 1);
            s_w[c2][tid] = valid ? wgt : 0.f;
            s_a[c2][tid] = yyc*Wd + xcc;
        }
    }
    __syncthreads();
    int hwi = tid & 63;
    int cl = tid >> 6;
    float w0 = s_w[0][hwi], w1 = s_w[1][hwi], w2 = s_w[2][hwi], w3 = s_w[3][hwi];
    int a0 = s_a[0][hwi], a1 = s_a[1][hwi], a2 = s_a[2][hwi], a3 = s_a[3][hwi];
    for (int c = cl; c < C; c += 4) {
        const float* xp = x + ((long)b*C + c)*N;
        float v = w0*xp[a0] + w1*xp[a1] + w2*xp[a2] + w3*xp[a3];
        col[((long)b*C*9 + c*9 + k)*N + hw0 + hwi] = v;
    }
}

// ---------------- launch ----------------
extern "C" void kernel_launch(void* const* d_in, const int* in_sizes, int n_in,
                              void* d_out, int out_size)
{
    (void)in_sizes; (void)n_in; (void)out_size;
    const float* t     = (const float*)d_in[0];
    const float* s     = (const float*)d_in[1];
    const float* tq_w  = (const float*)d_in[2];
    const float* tq_b  = (const float*)d_in[3];
    const float* tk_w  = (const float*)d_in[4];
    const float* tk_b  = (const float*)d_in[5];
    const float* tv_w  = (const float*)d_in[6];
    const float* tv_b  = (const float*)d_in[7];
    const float* sq_w  = (const float*)d_in[8];
    const float* sq_b  = (const float*)d_in[9];
    const float* sk_w  = (const float*)d_in[10];
    const float* sk_b  = (const float*)d_in[11];
    const float* sv_w  = (const float*)d_in[12];
    const float* sv_b  = (const float*)d_in[13];
    const float* t_off_w = (const float*)d_in[14];
    const float* t_off_b = (const float*)d_in[15];
    const float* t_dcn_w = (const float*)d_in[16];
    const float* t_dcn_b = (const float*)d_in[17];
    const float* s_off_w = (const float*)d_in[18];
    const float* s_off_b = (const float*)d_in[19];
    const float* s_dcn_w = (const float*)d_in[20];
    const float* s_dcn_b = (const float*)d_in[21];
    float* out_t = (float*)d_out;
    float* out_s = out_t + (long)BATCH*C*NT;

    float *q_t, *k_t, *q_s, *k_s, *v_t, *v_s, *att_t, *att_s;
    float *Gt, *Gs, *Mm, *at_, *as_, *off_t, *off_s, *col_t, *col_s;
    cudaGetSymbolAddress((void**)&q_t,  g_q_t);
    cudaGetSymbolAddress((void**)&k_t,  g_k_t);
    cudaGetSymbolAddress((void**)&q_s,  g_q_s);
    cudaGetSymbolAddress((void**)&k_s,  g_k_s);
    cudaGetSymbolAddress((void**)&v_t,  g_v_t);
    cudaGetSymbolAddress((void**)&v_s,  g_v_s);
    cudaGetSymbolAddress((void**)&att_t, g_att_t);
    cudaGetSymbolAddress((void**)&att_s, g_att_s);
    cudaGetSymbolAddress((void**)&Gt,   g_Gt);
    cudaGetSymbolAddress((void**)&Gs,   g_Gs);
    cudaGetSymbolAddress((void**)&Mm,   g_M);
    cudaGetSymbolAddress((void**)&at_,  g_at);
    cudaGetSymbolAddress((void**)&as_,  g_as);
    cudaGetSymbolAddress((void**)&off_t, g_off_t);
    cudaGetSymbolAddress((void**)&off_s, g_off_s);
    cudaGetSymbolAddress((void**)&col_t, g_col_t);
    cudaGetSymbolAddress((void**)&col_s, g_col_s);

    const long CNT = (long)C*NT, CNS = (long)C*NS, CC = (long)C*C;

    // 1) q,k projections (layout (b,n,32)) and v projections (layout (b,c,n))
    qk_conv<<<dim3(NT/32, BATCH), 256>>>(t, tq_w, tq_b, q_t, NT);
    qk_conv<<<dim3(NT/32, BATCH), 256>>>(t, tk_w, tk_b, k_t, NT);
    qk_conv<<<dim3(NS/32, BATCH), 256>>>(s, sq_w, sq_b, q_s, NS);
    qk_conv<<<dim3(NS/32, BATCH), 256>>>(s, sk_w, sk_b, k_s, NS);
    gemm_big<64,128,false><<<dim3(NT/128, C/64, BATCH), 256>>>(tv_w, t, v_t, C, NT, C, 0, CNT, CNT, tv_b, nullptr, 0);
    gemm_big<128,128,false><<<dim3(NS/128, C/128, BATCH), 256>>>(sv_w, s, v_s, C, NS, C, 0, CNS, CNS, sv_b, nullptr, 0);

    // 2) spatial attention maps (softmax over batch axis!)
    spatial_att<<<dim3(NT/16, NT/16), 256>>>(q_t, k_t, att_t, NT);
    spatial_att<<<dim3(NS/16, NS/16), 256>>>(q_s, k_s, att_s, NS);

    // 3) spatial out = v @ att  -> g_at / g_as
    gemm_big<64,128,false><<<dim3(NT/128, C/64, BATCH), 256>>>(v_t, att_t, at_, C, NT, NT, CNT, (long)NT*NT, CNT, nullptr, nullptr, 0);
    gemm_big<128,128,false><<<dim3(NS/128, C/128, BATCH), 256>>>(v_s, att_s, as_, C, NS, NS, CNS, (long)NS*NS, CNS, nullptr, nullptr, 0);

    // 4) grams G = f f^T, column-softmax, combine M = A_t + A_s
    gemm_big<64,128,true><<<dim3(C/128, C/64, BATCH), 256>>>(t, t, Gt, C, C, NT, CNT, CNT, CC, nullptr, nullptr, 0);
    gemm_big<64,128,true><<<dim3(C/128, C/64, BATCH), 256>>>(s, s, Gs, C, C, NS, CNS, CNS, CC, nullptr, nullptr, 0);
    softmax_col_add<<<dim3(C/32, BATCH), 256>>>(Gt, Mm, 0);
    softmax_col_add<<<dim3(C/32, BATCH), 256>>>(Gs, Mm, 1);

    // 5) at = (v@att) + t + M@t ; asr = (v@att) + s + M@s   (residual folded into epilogue)
    gemm_big<64,128,false><<<dim3(NT/128, C/64, BATCH), 256>>>(Mm, t, at_, C, NT, C, CC, CNT, CNT, nullptr, t, 1);
    gemm_big<128,128,false><<<dim3(NS/128, C/128, BATCH), 256>>>(Mm, s, as_, C, NS, C, CC, CNS, CNS, nullptr, s, 1);

    // 6) offset/mask conv (27 channels)
    conv3x3_off<<<dim3(16, BATCH), 256>>>(at_, t_off_w, t_off_b, off_t, 16, 16);
    conv3x3_off<<<dim3(32, BATCH), 256>>>(as_, s_off_w, s_off_b, off_s, 32, 32);

    // 7) deformable bilinear sampling -> im2col
    dcn_sample<<<dim3(NT/64, 9, BATCH), 256>>>(at_, off_t, col_t, 16, 16);
    dcn_sample<<<dim3(NS/64, 9, BATCH), 256>>>(as_, off_s, col_s, 32, 32);

    // 8) dcn main GEMM: out = W(256x2304) @ col + bias  -> final outputs
    gemm_big<64,128,false><<<dim3(NT/128, C/64, BATCH), 256>>>(t_dcn_w, col_t, out_t, C, NT, C*9, 0, (long)C*9*NT, CNT, t_dcn_b, nullptr, 0);
    gemm_big<128,128,false><<<dim3(NS/128, C/128, BATCH), 256>>>(s_dcn_w, col_s, out_s, C, NS, C*9, 0, (long)C*9*NS, CNS, s_dcn_b, nullptr, 0);
}

// round 4
// speedup vs baseline: 1.8816x; 1.2749x over previous
#include <cuda_runtime.h>
#include <cuda_bf16.h>
#include <math.h>
#include <stdint.h>

#define BATCH 16
#define C 256
#define CQK 32
#define NT 256   /* 16x16 */
#define NS 1024  /* 32x32 */

// ---------------- scratch (static device memory; allowed) ----------------
__device__ float g_q_t[BATCH*NT*CQK];
__device__ float g_k_t[BATCH*NT*CQK];
__device__ float g_q_s[BATCH*NS*CQK];
__device__ float g_k_s[BATCH*NS*CQK];
__device__ float g_v_t[BATCH*C*NT];
__device__ float g_v_s[BATCH*C*NS];
__device__ float g_att_t[BATCH*NT*NT];
__device__ float g_att_s[(size_t)BATCH*NS*NS];
__device__ float g_Gt[BATCH*C*C];
__device__ float g_Gs[BATCH*C*C];
__device__ float g_M[BATCH*C*C];
__device__ float g_at[BATCH*C*NT];
__device__ float g_as[BATCH*C*NS];
__device__ float g_off_t[BATCH*27*NT];
__device__ float g_off_s[BATCH*27*NS];
__device__ float g_col_t[(size_t)BATCH*C*9*NT];
__device__ float g_col_s[(size_t)BATCH*C*9*NS];

// ---------------- helpers ----------------
__device__ __forceinline__ uint32_t pack_bf16(float a, float b) {
    uint32_t lo = __bfloat16_as_ushort(__float2bfloat16_rn(a));
    uint32_t hi = __bfloat16_as_ushort(__float2bfloat16_rn(b));
    return lo | (hi << 16);
}
__device__ __forceinline__ float bf16_hi_val(float a) {
    return __bfloat162float(__float2bfloat16_rn(a));
}

__device__ __forceinline__ void mma_bf16(float* c, const uint32_t* a, const uint32_t* b) {
    asm volatile(
        "mma.sync.aligned.m16n8k16.row.col.f32.bf16.bf16.f32 "
        "{%0,%1,%2,%3}, {%4,%5,%6,%7}, {%8,%9}, {%0,%1,%2,%3};"
        : "+f"(c[0]), "+f"(c[1]), "+f"(c[2]), "+f"(c[3])
        : "r"(a[0]), "r"(a[1]), "r"(a[2]), "r"(a[3]), "r"(b[0]), "r"(b[1]));
}

// ---- split-bf16 tensor GEMM: C[m,n] (+)= A[m,k]*B[k,n] (+bias)(+res), ~fp32-grade precision ----
// CTA 128x128x32, 8 warps (2m x 4n), warp tile 64x32, mma m16n8k16.
// Each fp32 input split a = a_hi(bf16) + a_lo(bf16); compute hh + hl + lh (3 MMAs / k16).
#define APITCH 20   /* uint32 per 16-k2 row, +4 pad: conflict-free fragment LDS */
#define SM_HALF (2*2*128*APITCH)          /* A region u32 count */
#define MMA_SMEM_BYTES (2*SM_HALF*4)      /* 81920 B */

__global__ __launch_bounds__(256)
void gemm_bf16x3(const float* __restrict__ A, const float* __restrict__ B,
                 float* __restrict__ Cc, int M, int N, int K,
                 long sA, long sB, long sC,
                 const float* __restrict__ bias,
                 const float* __restrict__ residual, int accumulate)
{
    extern __shared__ uint32_t sm_[];
    uint32_t* As = sm_;              // [buf][hl][128 m][APITCH]
    uint32_t* Bs = sm_ + SM_HALF;    // [buf][hl][128 n][APITCH]

    const float* Ab = A + (long)blockIdx.z*sA;
    const float* Bb = B + (long)blockIdx.z*sB;
    float* Cb = Cc + (long)blockIdx.z*sC;
    const float* Rb = residual ? residual + (long)blockIdx.z*sC : nullptr;

    int tid = threadIdx.x;
    int lane = tid & 31;
    int warp = tid >> 5;
    int wm = warp >> 2;          // 0..1
    int wn = warp & 3;           // 0..3
    int row0 = blockIdx.y * 128, col0 = blockIdx.x * 128;

    float acc[4][4][4];
    #pragma unroll
    for (int i = 0; i < 4; i++)
        #pragma unroll
        for (int j = 0; j < 4; j++)
            #pragma unroll
            for (int r = 0; r < 4; r++) acc[i][j][r] = 0.f;

    float4 ra[4];
    float rbv[4][4];

    auto fetchA = [&](int k0) {
        #pragma unroll
        for (int i = 0; i < 4; i++) {
            int slot = tid + i*256;          // 1024 = 128 m x 8 k4
            int m = slot >> 3, k4 = slot & 7;
            ra[i] = *(const float4*)&Ab[(long)(row0+m)*K + k0 + k4*4];
        }
    };
    auto storeA = [&](int buf) {
        #pragma unroll
        for (int i = 0; i < 4; i++) {
            int slot = tid + i*256;
            int m = slot >> 3, k4 = slot & 7;
            int k2 = k4*2;
            float x = ra[i].x, y = ra[i].y, z = ra[i].z, w = ra[i].w;
            uint2 h = make_uint2(pack_bf16(x, y), pack_bf16(z, w));
            uint2 l = make_uint2(pack_bf16(x - bf16_hi_val(x), y - bf16_hi_val(y)),
                                 pack_bf16(z - bf16_hi_val(z), w - bf16_hi_val(w)));
            *(uint2*)&As[((buf*2 + 0)*128 + m)*APITCH + k2] = h;
            *(uint2*)&As[((buf*2 + 1)*128 + m)*APITCH + k2] = l;
        }
    };
    auto fetchB = [&](int k0) {
        #pragma unroll
        for (int i = 0; i < 4; i++) {
            int slot = tid + i*256;          // 1024 = 8 kg x 128 n
            int n = slot & 127, kg = slot >> 7;
            #pragma unroll
            for (int j = 0; j < 4; j++)
                rbv[i][j] = Bb[(long)(k0 + kg*4 + j)*N + col0 + n];
        }
    };
    auto storeB = [&](int buf) {
        #pragma unroll
        for (int i = 0; i < 4; i++) {
            int slot = tid + i*256;
            int n = slot & 127, kg = slot >> 7;
            int k2 = kg*2;
            float v0 = rbv[i][0], v1 = rbv[i][1], v2 = rbv[i][2], v3 = rbv[i][3];
            uint2 h = make_uint2(pack_bf16(v0, v1), pack_bf16(v2, v3));
            uint2 l = make_uint2(pack_bf16(v0 - bf16_hi_val(v0), v1 - bf16_hi_val(v1)),
                                 pack_bf16(v2 - bf16_hi_val(v2), v3 - bf16_hi_val(v3)));
            *(uint2*)&Bs[((buf*2 + 0)*128 + n)*APITCH + k2] = h;
            *(uint2*)&Bs[((buf*2 + 1)*128 + n)*APITCH + k2] = l;
        }
    };
    auto compute = [&](int buf) {
        #pragma unroll
        for (int ks = 0; ks < 2; ks++) {     // two k16 steps per 32-k tile
            uint32_t ah[4][4], al[4][4], bh[4][2], bl[4][2];
            int c0i = ks*8 + (lane & 3);
            #pragma unroll
            for (int mt = 0; mt < 4; mt++) {
                int r = wm*64 + mt*16 + (lane >> 2);
                const uint32_t* ph = &As[((buf*2 + 0)*128)*APITCH];
                const uint32_t* pl = &As[((buf*2 + 1)*128)*APITCH];
                ah[mt][0] = ph[r*APITCH + c0i];
                ah[mt][1] = ph[(r+8)*APITCH + c0i];
                ah[mt][2] = ph[r*APITCH + c0i + 4];
                ah[mt][3] = ph[(r+8)*APITCH + c0i + 4];
                al[mt][0] = pl[r*APITCH + c0i];
                al[mt][1] = pl[(r+8)*APITCH + c0i];
                al[mt][2] = pl[r*APITCH + c0i + 4];
                al[mt][3] = pl[(r+8)*APITCH + c0i + 4];
            }
            #pragma unroll
            for (int nt = 0; nt < 4; nt++) {
                int n = wn*32 + nt*8 + (lane >> 2);
                const uint32_t* ph = &Bs[((buf*2 + 0)*128)*APITCH];
                const uint32_t* pl = &Bs[((buf*2 + 1)*128)*APITCH];
                bh[nt][0] = ph[n*APITCH + c0i];
                bh[nt][1] = ph[n*APITCH + c0i + 4];
                bl[nt][0] = pl[n*APITCH + c0i];
                bl[nt][1] = pl[n*APITCH + c0i + 4];
            }
            #pragma unroll
            for (int mt = 0; mt < 4; mt++)
                #pragma unroll
                for (int nt = 0; nt < 4; nt++) {
                    mma_bf16(acc[mt][nt], ah[mt], bh[nt]);
                    mma_bf16(acc[mt][nt], ah[mt], bl[nt]);
                    mma_bf16(acc[mt][nt], al[mt], bh[nt]);
                }
        }
    };

    fetchA(0); fetchB(0);
    storeA(0); storeB(0);
    __syncthreads();
    int buf = 0;
    for (int k0 = 0; k0 < K; k0 += 32) {
        bool has_next = (k0 + 32 < K);
        if (has_next) { fetchA(k0 + 32); fetchB(k0 + 32); }
        compute(buf);
        if (has_next) {
            storeA(buf ^ 1); storeB(buf ^ 1);
            __syncthreads();
            buf ^= 1;
        }
    }

    // epilogue
    #pragma unroll
    for (int mt = 0; mt < 4; mt++) {
        int r = row0 + wm*64 + mt*16 + (lane >> 2);
        float bv0 = bias ? bias[r] : 0.f;
        float bv1 = bias ? bias[r+8] : 0.f;
        #pragma unroll
        for (int nt = 0; nt < 4; nt++) {
            int n = col0 + wn*32 + nt*8 + (lane & 3)*2;
            long i0 = (long)r*N + n;
            long i1 = (long)(r+8)*N + n;
            float2 v0 = make_float2(acc[mt][nt][0] + bv0, acc[mt][nt][1] + bv0);
            float2 v1 = make_float2(acc[mt][nt][2] + bv1, acc[mt][nt][3] + bv1);
            if (accumulate) {
                float2 o0 = *(const float2*)&Cb[i0];
                float2 o1 = *(const float2*)&Cb[i1];
                v0.x += o0.x; v0.y += o0.y; v1.x += o1.x; v1.y += o1.y;
            }
            if (Rb) {
                float2 o0 = *(const float2*)&Rb[i0];
                float2 o1 = *(const float2*)&Rb[i1];
                v0.x += o0.x; v0.y += o0.y; v1.x += o1.x; v1.y += o1.y;
            }
            *(float2*)&Cb[i0] = v0;
            *(float2*)&Cb[i1] = v1;
        }
    }
}

// ---------------- 1x1 conv producing (b, n, 32) layout for q/k ----------------
__global__ void qk_conv(const float* __restrict__ x, const float* __restrict__ W,
                        const float* __restrict__ bias, float* __restrict__ out, int N)
{
    int b  = blockIdx.y;
    int n0 = blockIdx.x * 32;
    int nl = threadIdx.x & 31;
    int og = threadIdx.x >> 5;
    __shared__ float sx[32][33];
    __shared__ float sw[32][32];
    float acc[4] = {0.f, 0.f, 0.f, 0.f};
    for (int c0 = 0; c0 < C; c0 += 32) {
        #pragma unroll
        for (int i = 0; i < 4; i++) {
            sx[og*4+i][nl] = x[((long)b*C + c0 + og*4+i)*N + n0 + nl];
            sw[og*4+i][nl] = W[(og*4+i)*C + c0 + nl];
        }
        __syncthreads();
        #pragma unroll
        for (int cc = 0; cc < 32; cc++) {
            float xv = sx[cc][nl];
            #pragma unroll
            for (int i = 0; i < 4; i++) acc[i] += xv * sw[og*4+i][cc];
        }
        __syncthreads();
    }
    #pragma unroll
    for (int i = 0; i < 4; i++) {
        int o = og*4 + i;
        out[((long)b*N + n0 + nl)*CQK + o] = acc[i] + bias[o];
    }
}

// ---------------- fp32 tiled GEMM (kept for grams; exponent-sensitive path) ----------------
template<int BM, int BN, bool BT>
__global__ __launch_bounds__(256, 2)
void gemm_big(const float* __restrict__ A, const float* __restrict__ B,
              float* __restrict__ Cc, int M, int N, int K,
              long sA, long sB, long sC,
              const float* __restrict__ bias,
              const float* __restrict__ residual, int accumulate)
{
    constexpr int TM = BM/16, TN = BN/16;
    constexpr int AL2 = (BM*4)/256;
    constexpr int BL4 = (BN*2 + 255)/256;
    constexpr int BL2 = (BN*4 + 255)/256;
    constexpr bool BGUARD4 = (BN*2 < 256);
    constexpr bool BGUARD2 = (BN*4 < 256);

    const float* Ab = A + (long)blockIdx.z*sA;
    const float* Bb = B + (long)blockIdx.z*sB;
    float* Cb = Cc + (long)blockIdx.z*sC;
    const float* Rb = residual ? residual + (long)blockIdx.z*sC : nullptr;

    __shared__ float As[2][8][BM+4];
    __shared__ float Bs[2][8][BN+4];

    int tid = threadIdx.x;
    int tx = tid & 15, ty = tid >> 4;
    int row0 = blockIdx.y * BM, col0 = blockIdx.x * BN;

    float acc[TM][TN];
    #pragma unroll
    for (int i = 0; i < TM; i++)
        #pragma unroll
        for (int j = 0; j < TN; j++) acc[i][j] = 0.f;

    float2 ra[AL2];
    float4 rbv[(BT ? 1 : BL4)];
    float2 rbt[(BT ? BL2 : 1)];

    auto fetchA = [&](int k0) {
        #pragma unroll
        for (int i = 0; i < AL2; i++) {
            int l = tid + i*256;
            int m = l >> 2, k = (l & 3) * 2;
            ra[i] = *(const float2*)&Ab[(long)(row0+m)*K + k0 + k];
        }
    };
    auto storeA = [&](int buf) {
        #pragma unroll
        for (int i = 0; i < AL2; i++) {
            int l = tid + i*256;
            int m = l >> 2, k = (l & 3) * 2;
            As[buf][k][m]   = ra[i].x;
            As[buf][k+1][m] = ra[i].y;
        }
    };
    auto fetchB = [&](int k0) {
        if (!BT) {
            #pragma unroll
            for (int i = 0; i < BL4; i++) {
                int l = tid + i*256;
                if (!BGUARD4 || l < BN*2) {
                    int k = l / (BN/4), n = (l % (BN/4)) * 4;
                    rbv[i] = *(const float4*)&Bb[(long)(k0+k)*N + col0 + n];
                }
            }
        } else {
            #pragma unroll
            for (int i = 0; i < BL2; i++) {
                int l = tid + i*256;
                if (!BGUARD2 || l < BN*4) {
                    int n = l >> 2, k = (l & 3) * 2;
                    rbt[i] = *(const float2*)&Bb[(long)(col0+n)*K + k0 + k];
                }
            }
        }
    };
    auto storeB = [&](int buf) {
        if (!BT) {
            #pragma unroll
            for (int i = 0; i < BL4; i++) {
                int l = tid + i*256;
                if (!BGUARD4 || l < BN*2) {
                    int k = l / (BN/4), n = (l % (BN/4)) * 4;
                    *(float4*)&Bs[buf][k][n] = rbv[i];
                }
            }
        } else {
            #pragma unroll
            for (int i = 0; i < BL2; i++) {
                int l = tid + i*256;
                if (!BGUARD2 || l < BN*4) {
                    int n = l >> 2, k = (l & 3) * 2;
                    Bs[buf][k][n]   = rbt[i].x;
                    Bs[buf][k+1][n] = rbt[i].y;
                }
            }
        }
    };
    auto compute = [&](int buf) {
        #pragma unroll
        for (int kk = 0; kk < 8; kk++) {
            float a[TM], b[TN];
            #pragma unroll
            for (int i = 0; i < TM; i += 4)
                *(float4*)&a[i] = *(const float4*)&As[buf][kk][ty*TM + i];
            #pragma unroll
            for (int j = 0; j < TN; j += 4)
                *(float4*)&b[j] = *(const float4*)&Bs[buf][kk][tx*TN + j];
            #pragma unroll
            for (int i = 0; i < TM; i++)
                #pragma unroll
                for (int j = 0; j < TN; j++)
                    acc[i][j] += a[i] * b[j];
        }
    };

    fetchA(0); fetchB(0);
    storeA(0); storeB(0);
    __syncthreads();
    int buf = 0;
    for (int k0 = 0; k0 < K; k0 += 8) {
        bool has_next = (k0 + 8 < K);
        if (has_next) { fetchA(k0 + 8); fetchB(k0 + 8); }
        compute(buf);
        if (has_next) {
            storeA(buf ^ 1); storeB(buf ^ 1);
            __syncthreads();
            buf ^= 1;
        }
    }

    #pragma unroll
    for (int i = 0; i < TM; i++) {
        int r = row0 + ty*TM + i;
        float bv = bias ? bias[r] : 0.f;
        #pragma unroll
        for (int j = 0; j < TN; j += 4) {
            long idx = (long)r*N + col0 + tx*TN + j;
            float4 v = *(float4*)&acc[i][j];
            v.x += bv; v.y += bv; v.z += bv; v.w += bv;
            if (accumulate) {
                float4 o = *(const float4*)&Cb[idx];
                v.x += o.x; v.y += o.y; v.z += o.z; v.w += o.w;
            }
            if (Rb) {
                float4 o = *(const float4*)&Rb[idx];
                v.x += o.x; v.y += o.y; v.z += o.z; v.w += o.w;
            }
            *(float4*)&Cb[idx] = v;
        }
    }
}

// ---------------- spatial attention: logits (dot over 32) + softmax over BATCH axis ----------------
__global__ void spatial_att(const float* __restrict__ q, const float* __restrict__ k,
                            float* __restrict__ att, int N)
{
    int n0 = blockIdx.y * 16, m0 = blockIdx.x * 16;
    int tn = threadIdx.x >> 4, tm = threadIdx.x & 15;
    __shared__ float sq[16][33], sk[16][33];
    float logit[BATCH];
    for (int b = 0; b < BATCH; b++) {
        int i = threadIdx.x >> 5, c = threadIdx.x & 31;
        sq[i][c]     = q[((long)b*N + n0 + i)*CQK + c];
        sq[i + 8][c] = q[((long)b*N + n0 + i + 8)*CQK + c];
        sk[i][c]     = k[((long)b*N + m0 + i)*CQK + c];
        sk[i + 8][c] = k[((long)b*N + m0 + i + 8)*CQK + c];
        __syncthreads();
        float acc = 0.f;
        #pragma unroll
        for (int c2 = 0; c2 < 32; c2++) acc += sq[tn][c2] * sk[tm][c2];
        logit[b] = acc;
        __syncthreads();
    }
    float mx = logit[0];
    #pragma unroll
    for (int b = 1; b < BATCH; b++) mx = fmaxf(mx, logit[b]);
    float s = 0.f;
    #pragma unroll
    for (int b = 0; b < BATCH; b++) { logit[b] = expf(logit[b] - mx); s += logit[b]; }
    float inv = 1.f / s;
    #pragma unroll
    for (int b = 0; b < BATCH; b++)
        att[(long)b*N*N + (long)(n0 + tn)*N + m0 + tm] = logit[b] * inv;
}

// ---------------- column softmax of gram (over c for each (b,d)), optionally accumulating ----------------
__global__ void softmax_col_add(const float* __restrict__ G, float* __restrict__ out, int accumulate)
{
    int b = blockIdx.y;
    long base = (long)b * C * C;
    int lane = threadIdx.x & 31;
    int cg = threadIdx.x >> 5;
    int d = blockIdx.x * 32 + lane;
    float vals[32];
    float mx = -1e30f;
    #pragma unroll
    for (int i = 0; i < 32; i++) {
        vals[i] = G[base + (long)(cg*32 + i)*C + d];
        mx = fmaxf(mx, vals[i]);
    }
    __shared__ float red[8][32];
    red[cg][lane] = mx;
    __syncthreads();
    if (cg == 0) {
        float m = red[0][lane];
        #pragma unroll
        for (int j = 1; j < 8; j++) m = fmaxf(m, red[j][lane]);
        red[0][lane] = m;
    }
    __syncthreads();
    mx = red[0][lane];
    __syncthreads();
    float s = 0.f;
    #pragma unroll
    for (int i = 0; i < 32; i++) { vals[i] = expf(vals[i] - mx); s += vals[i]; }
    red[cg][lane] = s;
    __syncthreads();
    if (cg == 0) {
        float m = 0.f;
        #pragma unroll
        for (int j = 1; j < 8; j++) m += red[j][lane];
        red[0][lane] += m;
    }
    __syncthreads();
    float inv = 1.f / red[0][lane];
    #pragma unroll
    for (int i = 0; i < 32; i++) {
        long idx = base + (long)(cg*32 + i)*C + d;
        float v = vals[i] * inv;
        if (accumulate) v += out[idx];
        out[idx] = v;
    }
}

// ---------------- 3x3 conv, 27 output channels (offset/mask conv), SAME zero pad ----------------
__global__ void conv3x3_off(const float* __restrict__ x, const float* __restrict__ w,
                            const float* __restrict__ bias, float* __restrict__ out,
                            int H, int Wd)
{
    int b = blockIdx.y, h = blockIdx.x;
    int N = H * Wd;
    int wl = threadIdx.x % Wd;
    int og = threadIdx.x / Wd;
    int OCG = 256 / Wd;
    __shared__ float sx[16][3][32];
    __shared__ float sw[27][16][9];
    int ocs[4]; bool on[4];
    #pragma unroll
    for (int g = 0; g < 4; g++) { ocs[g] = og + g*OCG; on[g] = (ocs[g] < 27); }
    float acc[4] = {0.f, 0.f, 0.f, 0.f};
    for (int c0 = 0; c0 < C; c0 += 16) {
        for (int l = threadIdx.x; l < 27*16*9; l += 256) {
            int oc = l / 144, rem = l % 144, cc = rem / 9, p = rem % 9;
            sw[oc][cc][p] = w[((long)oc*C + c0 + cc)*9 + p];
        }
        for (int l = threadIdx.x; l < 16*3*Wd; l += 256) {
            int cc = l / (3*Wd), r = (l / Wd) % 3, ww = l % Wd;
            int hh = h + r - 1;
            float v = 0.f;
            if (hh >= 0 && hh < H) v = x[((long)b*C + c0 + cc)*N + hh*Wd + ww];
            sx[cc][r][ww] = v;
        }
        __syncthreads();
        for (int cc = 0; cc < 16; cc++) {
            #pragma unroll
            for (int p = 0; p < 9; p++) {
                int dy = p / 3, dx = p % 3;
                int wloc = wl + dx - 1;
                float xv = (wloc >= 0 && wloc < Wd) ? sx[cc][dy][wloc] : 0.f;
                #pragma unroll
                for (int g = 0; g < 4; g++)
                    if (on[g]) acc[g] += xv * sw[ocs[g]][cc][p];
            }
        }
        __syncthreads();
    }
    #pragma unroll
    for (int g = 0; g < 4; g++)
        if (on[g]) out[((long)b*27 + ocs[g])*N + h*Wd + wl] = acc[g] + bias[ocs[g]];
}

// ---------------- deformable sampling -> im2col: col[b, c*9+k, hw] ----------------
__global__ void dcn_sample(const float* __restrict__ x, const float* __restrict__ off,
                           float* __restrict__ col, int H, int Wd)
{
    int b = blockIdx.z, k = blockIdx.y;
    int N = H * Wd;
    int hw0 = blockIdx.x * 64;
    __shared__ float s_w[4][64];
    __shared__ int s_a[4][64];
    int tid = threadIdx.x;
    if (tid < 64) {
        int hw = hw0 + tid;
        int h = hw / Wd, ww = hw % Wd;
        long ob = (long)b * 27 * N;
        float oy = off[ob + (2*k)*N + hw];
        float ox = off[ob + (2*k + 1)*N + hw];
        float mz = off[ob + (18 + k)*N + hw];
        float mk = 1.f / (1.f + expf(-mz));
        float y  = (float)(h - 1 + k/3) + oy;
        float xx = (float)(ww - 1 + k%3) + ox;
        float y0f = floorf(y), x0f = floorf(xx);
        float wy = y - y0f, wx = xx - x0f;
        int y0 = (int)y0f, x0 = (int)x0f;
        #pragma unroll
        for (int c2 = 0; c2 < 4; c2++) {
            int dy = c2 >> 1, dx = c2 & 1;
            int yy = y0 + dy, xc = x0 + dx;
            bool valid = (yy >= 0 && yy < H && xc >= 0 && xc < Wd);
            float wgt = (dy ? wy : 1.f - wy) * (dx ? wx : 1.f - wx) * mk;
            int yyc = min(max(yy, 0), H - 1), xcc = min(max(xc, 0), Wd - 1);
            s_w[c2][tid] = valid ? wgt : 0.f;
            s_a[c2][tid] = yyc*Wd + xcc;
        }
    }
    __syncthreads();
    int hwi = tid & 63;
    int cl = tid >> 6;
    float w0 = s_w[0][hwi], w1 = s_w[1][hwi], w2 = s_w[2][hwi], w3 = s_w[3][hwi];
    int a0 = s_a[0][hwi], a1 = s_a[1][hwi], a2 = s_a[2][hwi], a3 = s_a[3][hwi];
    for (int c = cl; c < C; c += 4) {
        const float* xp = x + ((long)b*C + c)*N;
        float v = w0*xp[a0] + w1*xp[a1] + w2*xp[a2] + w3*xp[a3];
        col[((long)b*C*9 + c*9 + k)*N + hw0 + hwi] = v;
    }
}

// ---------------- launch ----------------
extern "C" void kernel_launch(void* const* d_in, const int* in_sizes, int n_in,
                              void* d_out, int out_size)
{
    (void)in_sizes; (void)n_in; (void)out_size;
    const float* t     = (const float*)d_in[0];
    const float* s     = (const float*)d_in[1];
    const float* tq_w  = (const float*)d_in[2];
    const float* tq_b  = (const float*)d_in[3];
    const float* tk_w  = (const float*)d_in[4];
    const float* tk_b  = (const float*)d_in[5];
    const float* tv_w  = (const float*)d_in[6];
    const float* tv_b  = (const float*)d_in[7];
    const float* sq_w  = (const float*)d_in[8];
    const float* sq_b  = (const float*)d_in[9];
    const float* sk_w  = (const float*)d_in[10];
    const float* sk_b  = (const float*)d_in[11];
    const float* sv_w  = (const float*)d_in[12];
    const float* sv_b  = (const float*)d_in[13];
    const float* t_off_w = (const float*)d_in[14];
    const float* t_off_b = (const float*)d_in[15];
    const float* t_dcn_w = (const float*)d_in[16];
    const float* t_dcn_b = (const float*)d_in[17];
    const float* s_off_w = (const float*)d_in[18];
    const float* s_off_b = (const float*)d_in[19];
    const float* s_dcn_w = (const float*)d_in[20];
    const float* s_dcn_b = (const float*)d_in[21];
    float* out_t = (float*)d_out;
    float* out_s = out_t + (long)BATCH*C*NT;

    float *q_t, *k_t, *q_s, *k_s, *v_t, *v_s, *att_t, *att_s;
    float *Gt, *Gs, *Mm, *at_, *as_, *off_t, *off_s, *col_t, *col_s;
    cudaGetSymbolAddress((void**)&q_t,  g_q_t);
    cudaGetSymbolAddress((void**)&k_t,  g_k_t);
    cudaGetSymbolAddress((void**)&q_s,  g_q_s);
    cudaGetSymbolAddress((void**)&k_s,  g_k_s);
    cudaGetSymbolAddress((void**)&v_t,  g_v_t);
    cudaGetSymbolAddress((void**)&v_s,  g_v_s);
    cudaGetSymbolAddress((void**)&att_t, g_att_t);
    cudaGetSymbolAddress((void**)&att_s, g_att_s);
    cudaGetSymbolAddress((void**)&Gt,   g_Gt);
    cudaGetSymbolAddress((void**)&Gs,   g_Gs);
    cudaGetSymbolAddress((void**)&Mm,   g_M);
    cudaGetSymbolAddress((void**)&at_,  g_at);
    cudaGetSymbolAddress((void**)&as_,  g_as);
    cudaGetSymbolAddress((void**)&off_t, g_off_t);
    cudaGetSymbolAddress((void**)&off_s, g_off_s);
    cudaGetSymbolAddress((void**)&col_t, g_col_t);
    cudaGetSymbolAddress((void**)&col_s, g_col_s);

    const long CNT = (long)C*NT, CNS = (long)C*NS, CC = (long)C*C;

    cudaFuncSetAttribute(gemm_bf16x3, cudaFuncAttributeMaxDynamicSharedMemorySize, MMA_SMEM_BYTES);

    // 1) q,k projections (layout (b,n,32)) and v projections (layout (b,c,n))
    qk_conv<<<dim3(NT/32, BATCH), 256>>>(t, tq_w, tq_b, q_t, NT);
    qk_conv<<<dim3(NT/32, BATCH), 256>>>(t, tk_w, tk_b, k_t, NT);
    qk_conv<<<dim3(NS/32, BATCH), 256>>>(s, sq_w, sq_b, q_s, NS);
    qk_conv<<<dim3(NS/32, BATCH), 256>>>(s, sk_w, sk_b, k_s, NS);
    gemm_bf16x3<<<dim3(NT/128, C/128, BATCH), 256, MMA_SMEM_BYTES>>>(tv_w, t, v_t, C, NT, C, 0, CNT, CNT, tv_b, nullptr, 0);
    gemm_bf16x3<<<dim3(NS/128, C/128, BATCH), 256, MMA_SMEM_BYTES>>>(sv_w, s, v_s, C, NS, C, 0, CNS, CNS, sv_b, nullptr, 0);

    // 2) spatial attention maps (softmax over batch axis!) — fp32, exponent-sensitive
    spatial_att<<<dim3(NT/16, NT/16), 256>>>(q_t, k_t, att_t, NT);
    spatial_att<<<dim3(NS/16, NS/16), 256>>>(q_s, k_s, att_s, NS);

    // 3) spatial out = v @ att
    gemm_bf16x3<<<dim3(NT/128, C/128, BATCH), 256, MMA_SMEM_BYTES>>>(v_t, att_t, at_, C, NT, NT, CNT, (long)NT*NT, CNT, nullptr, nullptr, 0);
    gemm_bf16x3<<<dim3(NS/128, C/128, BATCH), 256, MMA_SMEM_BYTES>>>(v_s, att_s, as_, C, NS, NS, CNS, (long)NS*NS, CNS, nullptr, nullptr, 0);

    // 4) grams G = f f^T (kept fp32 — feeds softmax), column-softmax, combine M = A_t + A_s
    gemm_big<64,128,true><<<dim3(C/128, C/64, BATCH), 256>>>(t, t, Gt, C, C, NT, CNT, CNT, CC, nullptr, nullptr, 0);
    gemm_big<64,128,true><<<dim3(C/128, C/64, BATCH), 256>>>(s, s, Gs, C, C, NS, CNS, CNS, CC, nullptr, nullptr, 0);
    softmax_col_add<<<dim3(C/32, BATCH), 256>>>(Gt, Mm, 0);
    softmax_col_add<<<dim3(C/32, BATCH), 256>>>(Gs, Mm, 1);

    // 5) at = (v@att) + t + M@t ; asr = (v@att) + s + M@s   (residual folded into epilogue)
    gemm_bf16x3<<<dim3(NT/128, C/128, BATCH), 256, MMA_SMEM_BYTES>>>(Mm, t, at_, C, NT, C, CC, CNT, CNT, nullptr, t, 1);
    gemm_bf16x3<<<dim3(NS/128, C/128, BATCH), 256, MMA_SMEM_BYTES>>>(Mm, s, as_, C, NS, C, CC, CNS, CNS, nullptr, s, 1);

    // 6) offset/mask conv (27 channels)
    conv3x3_off<<<dim3(16, BATCH), 256>>>(at_, t_off_w, t_off_b, off_t, 16, 16);
    conv3x3_off<<<dim3(32, BATCH), 256>>>(as_, s_off_w, s_off_b, off_s, 32, 32);

    // 7) deformable bilinear sampling -> im2col
    dcn_sample<<<dim3(NT/64, 9, BATCH), 256>>>(at_, off_t, col_t, 16, 16);
    dcn_sample<<<dim3(NS/64, 9, BATCH), 256>>>(as_, off_s, col_s, 32, 32);

    // 8) dcn main GEMM: out = W(256x2304) @ col + bias
    gemm_bf16x3<<<dim3(NT/128, C/128, BATCH), 256, MMA_SMEM_BYTES>>>(t_dcn_w, col_t, out_t, C, NT, C*9, 0, (long)C*9*NT, CNT, t_dcn_b, nullptr, 0);
    gemm_bf16x3<<<dim3(NS/128, C/128, BATCH), 256, MMA_SMEM_BYTES>>>(s_dcn_w, col_s, out_s, C, NS, C*9, 0, (long)C*9*NS, CNS, s_dcn_b, nullptr, 0);
}

// round 6
// speedup vs baseline: 2.0649x; 1.0974x over previous
#include <cuda_runtime.h>
#include <cuda_bf16.h>
#include <math.h>
#include <stdint.h>

#define BATCH 16
#define C 256
#define CQK 32
#define NT 256   /* 16x16 */
#define NS 1024  /* 32x32 */

// ---------------- scratch (static device memory; allowed) ----------------
__device__ float g_q_t[BATCH*NT*CQK];
__device__ float g_k_t[BATCH*NT*CQK];
__device__ float g_q_s[BATCH*NS*CQK];
__device__ float g_k_s[BATCH*NS*CQK];
__device__ float g_v_t[BATCH*C*NT];
__device__ float g_v_s[BATCH*C*NS];
__device__ float g_att_t[BATCH*NT*NT];
__device__ float g_att_s[(size_t)BATCH*NS*NS];
__device__ float g_Gt[BATCH*C*C];
__device__ float g_Gs[BATCH*C*C];
__device__ float g_M[BATCH*C*C];
__device__ float g_at[BATCH*C*NT];
__device__ float g_as[BATCH*C*NS];
__device__ float g_off_t[BATCH*27*NT];
__device__ float g_off_s[BATCH*27*NS];
__device__ float g_col_t[(size_t)BATCH*C*9*NT];
__device__ float g_col_s[(size_t)BATCH*C*9*NS];

// ---------------- helpers ----------------
__device__ __forceinline__ uint32_t pack_bf16(float a, float b) {
    uint32_t lo = __bfloat16_as_ushort(__float2bfloat16_rn(a));
    uint32_t hi = __bfloat16_as_ushort(__float2bfloat16_rn(b));
    return lo | (hi << 16);
}
__device__ __forceinline__ float bf16_hi_val(float a) {
    return __bfloat162float(__float2bfloat16_rn(a));
}
__device__ __forceinline__ void mma_bf16(float* c, const uint32_t* a, const uint32_t* b) {
    asm volatile(
        "mma.sync.aligned.m16n8k16.row.col.f32.bf16.bf16.f32 "
        "{%0,%1,%2,%3}, {%4,%5,%6,%7}, {%8,%9}, {%0,%1,%2,%3};"
        : "+f"(c[0]), "+f"(c[1]), "+f"(c[2]), "+f"(c[3])
        : "r"(a[0]), "r"(a[1]), "r"(a[2]), "r"(a[3]), "r"(b[0]), "r"(b[1]));
}

// ---- split-bf16 tensor GEMM: C[m,n] (+)= A[m,k]*B[k,n] (+bias)(+res), ~fp32-grade precision ----
// CTA 128 x BN x 32. BN=128: 8 warps 2m x 4n (warp 64x32). BN=64: 4m x 2n (warp 32x32).
// BT=true: B stored (N x K) row-major (used transposed) -> vectorized fetch.
#define APITCH 20   /* u32 per row of a k32 tile (+4 pad): conflict-free fragments */
#define A_WORDS (2*2*128*APITCH)

template<int BN, bool BT>
__global__ __launch_bounds__(256)
void gemm_bf16x3(const float* __restrict__ A, const float* __restrict__ B,
                 float* __restrict__ Cc, int M_, int N, int K,
                 long sA, long sB, long sC,
                 const float* __restrict__ bias,
                 const float* __restrict__ residual, int accumulate)
{
    constexpr int WN  = BN / 32;          // warps along n
    constexpr int MT  = (BN == 128) ? 4 : 2;
    constexpr int BIT = (BN * 8) / 256;   // B load iters
    constexpr int BSH = (BN == 128) ? 7 : 6;

    extern __shared__ uint32_t sm_[];
    uint32_t* As = sm_;                   // [buf][hl][128][APITCH]
    uint32_t* Bs = sm_ + A_WORDS;         // [buf][hl][BN][APITCH]

    const float* Ab = A + (long)blockIdx.z*sA;
    const float* Bb = B + (long)blockIdx.z*sB;
    float* Cb = Cc + (long)blockIdx.z*sC;
    const float* Rb = residual ? residual + (long)blockIdx.z*sC : nullptr;

    int tid = threadIdx.x;
    int lane = tid & 31;
    int warp = tid >> 5;
    int wm = warp / WN;
    int wn = warp % WN;
    int row0 = blockIdx.y * 128, col0 = blockIdx.x * BN;

    float acc[MT][4][4];
    #pragma unroll
    for (int i = 0; i < MT; i++)
        #pragma unroll
        for (int j = 0; j < 4; j++)
            #pragma unroll
            for (int r = 0; r < 4; r++) acc[i][j][r] = 0.f;

    float4 fa[4];
    float4 fbt[BT ? BIT : 1];
    float  fbn[BT ? 1 : BIT][4];

    auto fetchA = [&](int k0) {
        #pragma unroll
        for (int i = 0; i < 4; i++) {
            int slot = tid + i*256;                 // 1024 = 128m x 8 k4
            int m = slot >> 3, k4 = slot & 7;
            fa[i] = *(const float4*)&Ab[(long)(row0+m)*K + k0 + k4*4];
        }
    };
    auto storeA = [&](int buf) {
        #pragma unroll
        for (int i = 0; i < 4; i++) {
            int slot = tid + i*256;
            int m = slot >> 3, k2 = (slot & 7) * 2;
            float x = fa[i].x, y = fa[i].y, z = fa[i].z, w = fa[i].w;
            uint2 h = make_uint2(pack_bf16(x, y), pack_bf16(z, w));
            uint2 l = make_uint2(pack_bf16(x - bf16_hi_val(x), y - bf16_hi_val(y)),
                                 pack_bf16(z - bf16_hi_val(z), w - bf16_hi_val(w)));
            *(uint2*)&As[((buf*2 + 0)*128 + m)*APITCH + k2] = h;
            *(uint2*)&As[((buf*2 + 1)*128 + m)*APITCH + k2] = l;
        }
    };
    auto fetchB = [&](int k0) {
        if (BT) {
            #pragma unroll
            for (int i = 0; i < BIT; i++) {
                int slot = tid + i*256;             // BN*8 = n x k4
                int k4 = slot & 7, n = slot >> 3;
                fbt[i] = *(const float4*)&Bb[(long)(col0+n)*K + k0 + k4*4];
            }
        } else {
            #pragma unroll
            for (int i = 0; i < BIT; i++) {
                int slot = tid + i*256;             // kg x n
                int n = slot & (BN-1), kg = slot >> BSH;
                #pragma unroll
                for (int j = 0; j < 4; j++)
                    fbn[i][j] = Bb[(long)(k0 + kg*4 + j)*N + col0 + n];
            }
        }
    };
    auto storeB = [&](int buf) {
        #pragma unroll
        for (int i = 0; i < BIT; i++) {
            int slot = tid + i*256;
            int n, k2;
            float v0, v1, v2, v3;
            if (BT) {
                n = slot >> 3; k2 = (slot & 7) * 2;
                v0 = fbt[i].x; v1 = fbt[i].y; v2 = fbt[i].z; v3 = fbt[i].w;
            } else {
                n = slot & (BN-1); k2 = (slot >> BSH) * 2;
                v0 = fbn[i][0]; v1 = fbn[i][1]; v2 = fbn[i][2]; v3 = fbn[i][3];
            }
            uint2 h = make_uint2(pack_bf16(v0, v1), pack_bf16(v2, v3));
            uint2 l = make_uint2(pack_bf16(v0 - bf16_hi_val(v0), v1 - bf16_hi_val(v1)),
                                 pack_bf16(v2 - bf16_hi_val(v2), v3 - bf16_hi_val(v3)));
            *(uint2*)&Bs[((buf*2 + 0)*BN + n)*APITCH + k2] = h;
            *(uint2*)&Bs[((buf*2 + 1)*BN + n)*APITCH + k2] = l;
        }
    };
    auto compute = [&](int buf) {
        #pragma unroll
        for (int ks = 0; ks < 2; ks++) {
            uint32_t ah[MT][4], al[MT][4], bh[4][2], bl[4][2];
            int ca = ks*8 + (lane & 3);
            const uint32_t* pah = &As[(buf*2 + 0)*128*APITCH];
            const uint32_t* pal = &As[(buf*2 + 1)*128*APITCH];
            #pragma unroll
            for (int mt = 0; mt < MT; mt++) {
                int r = wm*(MT*16) + mt*16 + (lane >> 2);
                ah[mt][0] = pah[r*APITCH + ca];
                ah[mt][1] = pah[(r+8)*APITCH + ca];
                ah[mt][2] = pah[r*APITCH + ca + 4];
                ah[mt][3] = pah[(r+8)*APITCH + ca + 4];
                al[mt][0] = pal[r*APITCH + ca];
                al[mt][1] = pal[(r+8)*APITCH + ca];
                al[mt][2] = pal[r*APITCH + ca + 4];
                al[mt][3] = pal[(r+8)*APITCH + ca + 4];
            }
            const uint32_t* pbh = &Bs[(buf*2 + 0)*BN*APITCH];
            const uint32_t* pbl = &Bs[(buf*2 + 1)*BN*APITCH];
            #pragma unroll
            for (int nt = 0; nt < 4; nt++) {
                int n = wn*32 + nt*8 + (lane >> 2);
                bh[nt][0] = pbh[n*APITCH + ca];
                bh[nt][1] = pbh[n*APITCH + ca + 4];
                bl[nt][0] = pbl[n*APITCH + ca];
                bl[nt][1] = pbl[n*APITCH + ca + 4];
            }
            #pragma unroll
            for (int mt = 0; mt < MT; mt++)
                #pragma unroll
                for (int nt = 0; nt < 4; nt++) {
                    mma_bf16(acc[mt][nt], ah[mt], bh[nt]);
                    mma_bf16(acc[mt][nt], ah[mt], bl[nt]);
                    mma_bf16(acc[mt][nt], al[mt], bh[nt]);
                }
        }
    };

    fetchA(0); fetchB(0);
    storeA(0); storeB(0);
    __syncthreads();
    int buf = 0;
    for (int k0 = 0; k0 < K; k0 += 32) {
        bool has_next = (k0 + 32 < K);
        if (has_next) { fetchA(k0 + 32); fetchB(k0 + 32); }
        compute(buf);
        if (has_next) {
            storeA(buf ^ 1); storeB(buf ^ 1);
            __syncthreads();
            buf ^= 1;
        }
    }

    // epilogue
    #pragma unroll
    for (int mt = 0; mt < MT; mt++) {
        int r = row0 + wm*(MT*16) + mt*16 + (lane >> 2);
        float bv0 = bias ? bias[r] : 0.f;
        float bv1 = bias ? bias[r+8] : 0.f;
        #pragma unroll
        for (int nt = 0; nt < 4; nt++) {
            int n = col0 + wn*32 + nt*8 + (lane & 3)*2;
            long i0 = (long)r*N + n;
            long i1 = (long)(r+8)*N + n;
            float2 v0 = make_float2(acc[mt][nt][0] + bv0, acc[mt][nt][1] + bv0);
            float2 v1 = make_float2(acc[mt][nt][2] + bv1, acc[mt][nt][3] + bv1);
            if (accumulate) {
                float2 o0 = *(const float2*)&Cb[i0];
                float2 o1 = *(const float2*)&Cb[i1];
                v0.x += o0.x; v0.y += o0.y; v1.x += o1.x; v1.y += o1.y;
            }
            if (Rb) {
                float2 o0 = *(const float2*)&Rb[i0];
                float2 o1 = *(const float2*)&Rb[i1];
                v0.x += o0.x; v0.y += o0.y; v1.x += o1.x; v1.y += o1.y;
            }
            *(float2*)&Cb[i0] = v0;
            *(float2*)&Cb[i1] = v1;
        }
    }
}

#define GSM_BYTES(BN) ((A_WORDS + 2*2*(BN)*APITCH) * 4)

// ---------------- merged q+k 1x1 conv: out layout (b, n, 32) each ----------------
// grid (N/64, B), block 256: nl = tid&63 (pixel), og = tid>>6 (16 outputs each; og<2 -> q).
__global__ void qk_merged(const float* __restrict__ x,
                          const float* __restrict__ Wq, const float* __restrict__ qb,
                          const float* __restrict__ Wk, const float* __restrict__ kb,
                          float* __restrict__ qout, float* __restrict__ kout, int N)
{
    __shared__ float sx[64][65];
    __shared__ float sw[64][68];
    int b = blockIdx.y, n0 = blockIdx.x * 64;
    int nl = threadIdx.x & 63, og = threadIdx.x >> 6;
    float acc[16];
    #pragma unroll
    for (int i = 0; i < 16; i++) acc[i] = 0.f;

    for (int c0 = 0; c0 < C; c0 += 64) {
        #pragma unroll
        for (int l = threadIdx.x; l < 4096; l += 256) {
            int cc = l >> 6, nn = l & 63;
            sx[cc][nn] = x[((long)b*C + c0 + cc)*N + n0 + nn];
        }
        #pragma unroll
        for (int l = threadIdx.x; l < 4096; l += 256) {
            int o = l >> 6, cc = l & 63;
            const float* wp = (o < 32) ? (Wq + o*C) : (Wk + (o - 32)*C);
            sw[o][cc] = wp[c0 + cc];
        }
        __syncthreads();
        #pragma unroll
        for (int c4 = 0; c4 < 16; c4++) {
            float x0 = sx[c4*4+0][nl], x1 = sx[c4*4+1][nl];
            float x2 = sx[c4*4+2][nl], x3 = sx[c4*4+3][nl];
            #pragma unroll
            for (int i = 0; i < 16; i++) {
                float4 w = *(const float4*)&sw[og*16 + i][c4*4];
                acc[i] += x0*w.x + x1*w.y + x2*w.z + x3*w.w;
            }
        }
        __syncthreads();
    }
    long nb = (long)(b*N + n0 + nl) * CQK;
    if (og < 2) {
        #pragma unroll
        for (int i = 0; i < 16; i++) qout[nb + og*16 + i] = acc[i] + qb[og*16 + i];
    } else {
        #pragma unroll
        for (int i = 0; i < 16; i++) kout[nb + (og-2)*16 + i] = acc[i] + kb[(og-2)*16 + i];
    }
}

// ---------------- spatial attention v2: all batches preloaded, softmax over BATCH axis --------
// grid (N/16 m, N/16 n), block 256 (16n x 16m pairs). dyn smem 73728B.
#define SATT_SMEM (2*16*16*36*4)
__global__ void spatial_att2(const float* __restrict__ q, const float* __restrict__ k,
                             float* __restrict__ att, int N)
{
    extern __shared__ float sm[];
    float* sq = sm;                  // [b][i][36]
    float* sk = sm + 16*16*36;
    int n0 = blockIdx.y * 16, m0 = blockIdx.x * 16;
    int tn = threadIdx.x >> 4, tm = threadIdx.x & 15;

    for (int l = threadIdx.x; l < 16*16*32; l += 256) {
        int b = l >> 9, i = (l >> 5) & 15, c = l & 31;
        sq[(b*16 + i)*36 + c] = q[((long)(b*N + n0 + i))*CQK + c];
        sk[(b*16 + i)*36 + c] = k[((long)(b*N + m0 + i))*CQK + c];
    }
    __syncthreads();

    float logit[BATCH];
    #pragma unroll
    for (int b = 0; b < BATCH; b++) {
        const float* qr = &sq[(b*16 + tn)*36];
        const float* kr = &sk[(b*16 + tm)*36];
        float acc = 0.f;
        #pragma unroll
        for (int c4 = 0; c4 < 8; c4++) {
            float4 qa = *(const float4*)&qr[c4*4];
            float4 kb_ = *(const float4*)&kr[c4*4];
            acc += qa.x*kb_.x + qa.y*kb_.y + qa.z*kb_.z + qa.w*kb_.w;
        }
        logit[b] = acc;
    }
    float mx = logit[0];
    #pragma unroll
    for (int b = 1; b < BATCH; b++) mx = fmaxf(mx, logit[b]);
    float s = 0.f;
    #pragma unroll
    for (int b = 0; b < BATCH; b++) { logit[b] = expf(logit[b] - mx); s += logit[b]; }
    float inv = 1.f / s;
    #pragma unroll
    for (int b = 0; b < BATCH; b++)
        att[(long)b*N*N + (long)(n0 + tn)*N + m0 + tm] = logit[b] * inv;
}

// ---------------- column softmax of gram (over c for each (b,d)), optionally accumulating ----------------
__global__ void softmax_col_add(const float* __restrict__ G, float* __restrict__ out, int accumulate)
{
    int b = blockIdx.y;
    long base = (long)b * C * C;
    int lane = threadIdx.x & 31;
    int cg = threadIdx.x >> 5;
    int d = blockIdx.x * 32 + lane;
    float vals[32];
    float mx = -1e30f;
    #pragma unroll
    for (int i = 0; i < 32; i++) {
        vals[i] = G[base + (long)(cg*32 + i)*C + d];
        mx = fmaxf(mx, vals[i]);
    }
    __shared__ float red[8][32];
    red[cg][lane] = mx;
    __syncthreads();
    if (cg == 0) {
        float m = red[0][lane];
        #pragma unroll
        for (int j = 1; j < 8; j++) m = fmaxf(m, red[j][lane]);
        red[0][lane] = m;
    }
    __syncthreads();
    mx = red[0][lane];
    __syncthreads();
    float s = 0.f;
    #pragma unroll
    for (int i = 0; i < 32; i++) { vals[i] = expf(vals[i] - mx); s += vals[i]; }
    red[cg][lane] = s;
    __syncthreads();
    if (cg == 0) {
        float m = 0.f;
        #pragma unroll
        for (int j = 1; j < 8; j++) m += red[j][lane];
        red[0][lane] += m;
    }
    __syncthreads();
    float inv = 1.f / red[0][lane];
    #pragma unroll
    for (int i = 0; i < 32; i++) {
        long idx = base + (long)(cg*32 + i)*C + d;
        float v = vals[i] * inv;
        if (accumulate) v += out[idx];
        out[idx] = v;
    }
}

// ---------------- 3x3 conv, 27 output channels (offset/mask conv), SAME zero pad ----------------
__global__ void conv3x3_off(const float* __restrict__ x, const float* __restrict__ w,
                            const float* __restrict__ bias, float* __restrict__ out,
                            int H, int Wd)
{
    int b = blockIdx.y, h = blockIdx.x;
    int N = H * Wd;
    int wl = threadIdx.x % Wd;
    int og = threadIdx.x / Wd;
    int OCG = 256 / Wd;
    __shared__ float sx[16][3][32];
    __shared__ float sw[27][16][9];
    int ocs[4]; bool on[4];
    #pragma unroll
    for (int g = 0; g < 4; g++) { ocs[g] = og + g*OCG; on[g] = (ocs[g] < 27); }
    float acc[4] = {0.f, 0.f, 0.f, 0.f};
    for (int c0 = 0; c0 < C; c0 += 16) {
        for (int l = threadIdx.x; l < 27*16*9; l += 256) {
            int oc = l / 144, rem = l % 144, cc = rem / 9, p = rem % 9;
            sw[oc][cc][p] = w[((long)oc*C + c0 + cc)*9 + p];
        }
        for (int l = threadIdx.x; l < 16*3*Wd; l += 256) {
            int cc = l / (3*Wd), r = (l / Wd) % 3, ww = l % Wd;
            int hh = h + r - 1;
            float v = 0.f;
            if (hh >= 0 && hh < H) v = x[((long)b*C + c0 + cc)*N + hh*Wd + ww];
            sx[cc][r][ww] = v;
        }
        __syncthreads();
        for (int cc = 0; cc < 16; cc++) {
            #pragma unroll
            for (int p = 0; p < 9; p++) {
                int dy = p / 3, dx = p % 3;
                int wloc = wl + dx - 1;
                float xv = (wloc >= 0 && wloc < Wd) ? sx[cc][dy][wloc] : 0.f;
                #pragma unroll
                for (int g = 0; g < 4; g++)
                    if (on[g]) acc[g] += xv * sw[ocs[g]][cc][p];
            }
        }
        __syncthreads();
    }
    #pragma unroll
    for (int g = 0; g < 4; g++)
        if (on[g]) out[((long)b*27 + ocs[g])*N + h*Wd + wl] = acc[g] + bias[ocs[g]];
}

// ---------------- deformable sampling -> im2col: col[b, c*9+k, hw] ----------------
__global__ void dcn_sample(const float* __restrict__ x, const float* __restrict__ off,
                           float* __restrict__ col, int H, int Wd)
{
    int b = blockIdx.z, k = blockIdx.y;
    int N = H * Wd;
    int hw0 = blockIdx.x * 64;
    __shared__ float s_w[4][64];
    __shared__ int s_a[4][64];
    int tid = threadIdx.x;
    if (tid < 64) {
        int hw = hw0 + tid;
        int h = hw / Wd, ww = hw % Wd;
        long ob = (long)b * 27 * N;
        float oy = off[ob + (2*k)*N + hw];
        float ox = off[ob + (2*k + 1)*N + hw];
        float mz = off[ob + (18 + k)*N + hw];
        float mk = 1.f / (1.f + expf(-mz));
        float y  = (float)(h - 1 + k/3) + oy;
        float xx = (float)(ww - 1 + k%3) + ox;
        float y0f = floorf(y), x0f = floorf(xx);
        float wy = y - y0f, wx = xx - x0f;
        int y0 = (int)y0f, x0 = (int)x0f;
        #pragma unroll
        for (int c2 = 0; c2 < 4; c2++) {
            int dy = c2 >> 1, dx = c2 & 1;
            int yy = y0 + dy, xc = x0 + dx;
            bool valid = (yy >= 0 && yy < H && xc >= 0 && xc < Wd);
            float wgt = (dy ? wy : 1.f - wy) * (dx ? wx : 1.f - wx) * mk;
            int yyc = min(max(yy, 0), H - 1), xcc = min(max(xc, 0), Wd - 1);
            s_w[c2][tid] = valid ? wgt : 0.f;
            s_a[c2][tid] = yyc*Wd + xcc;
        }
    }
    __syncthreads();
    int hwi = tid & 63;
    int cl = tid >> 6;
    float w0 = s_w[0][hwi], w1 = s_w[1][hwi], w2 = s_w[2][hwi], w3 = s_w[3][hwi];
    int a0 = s_a[0][hwi], a1 = s_a[1][hwi], a2 = s_a[2][hwi], a3 = s_a[3][hwi];
    for (int c = cl; c < C; c += 4) {
        const float* xp = x + ((long)b*C + c)*N;
        float v = w0*xp[a0] + w1*xp[a1] + w2*xp[a2] + w3*xp[a3];
        col[((long)b*C*9 + c*9 + k)*N + hw0 + hwi] = v;
    }
}

// ---------------- launch ----------------
extern "C" void kernel_launch(void* const* d_in, const int* in_sizes, int n_in,
                              void* d_out, int out_size)
{
    (void)in_sizes; (void)n_in; (void)out_size;
    const float* t     = (const float*)d_in[0];
    const float* s     = (const float*)d_in[1];
    const float* tq_w  = (const float*)d_in[2];
    const float* tq_b  = (const float*)d_in[3];
    const float* tk_w  = (const float*)d_in[4];
    const float* tk_b  = (const float*)d_in[5];
    const float* tv_w  = (const float*)d_in[6];
    const float* tv_b  = (const float*)d_in[7];
    const float* sq_w  = (const float*)d_in[8];
    const float* sq_b  = (const float*)d_in[9];
    const float* sk_w  = (const float*)d_in[10];
    const float* sk_b  = (const float*)d_in[11];
    const float* sv_w  = (const float*)d_in[12];
    const float* sv_b  = (const float*)d_in[13];
    const float* t_off_w = (const float*)d_in[14];
    const float* t_off_b = (const float*)d_in[15];
    const float* t_dcn_w = (const float*)d_in[16];
    const float* t_dcn_b = (const float*)d_in[17];
    const float* s_off_w = (const float*)d_in[18];
    const float* s_off_b = (const float*)d_in[19];
    const float* s_dcn_w = (const float*)d_in[20];
    const float* s_dcn_b = (const float*)d_in[21];
    float* out_t = (float*)d_out;
    float* out_s = out_t + (long)BATCH*C*NT;

    float *q_t, *k_t, *q_s, *k_s, *v_t, *v_s, *att_t, *att_s;
    float *Gt, *Gs, *Mm, *at_, *as_, *off_t, *off_s, *col_t, *col_s;
    cudaGetSymbolAddress((void**)&q_t,  g_q_t);
    cudaGetSymbolAddress((void**)&k_t,  g_k_t);
    cudaGetSymbolAddress((void**)&q_s,  g_q_s);
    cudaGetSymbolAddress((void**)&k_s,  g_k_s);
    cudaGetSymbolAddress((void**)&v_t,  g_v_t);
    cudaGetSymbolAddress((void**)&v_s,  g_v_s);
    cudaGetSymbolAddress((void**)&att_t, g_att_t);
    cudaGetSymbolAddress((void**)&att_s, g_att_s);
    cudaGetSymbolAddress((void**)&Gt,   g_Gt);
    cudaGetSymbolAddress((void**)&Gs,   g_Gs);
    cudaGetSymbolAddress((void**)&Mm,   g_M);
    cudaGetSymbolAddress((void**)&at_,  g_at);
    cudaGetSymbolAddress((void**)&as_,  g_as);
    cudaGetSymbolAddress((void**)&off_t, g_off_t);
    cudaGetSymbolAddress((void**)&off_s, g_off_s);
    cudaGetSymbolAddress((void**)&col_t, g_col_t);
    cudaGetSymbolAddress((void**)&col_s, g_col_s);

    const long CNT = (long)C*NT, CNS = (long)C*NS, CC = (long)C*C;

    cudaFuncSetAttribute(gemm_bf16x3<128,false>, cudaFuncAttributeMaxDynamicSharedMemorySize, GSM_BYTES(128));
    cudaFuncSetAttribute(gemm_bf16x3<64,false>,  cudaFuncAttributeMaxDynamicSharedMemorySize, GSM_BYTES(64));
    cudaFuncSetAttribute(gemm_bf16x3<64,true>,   cudaFuncAttributeMaxDynamicSharedMemorySize, GSM_BYTES(64));
    cudaFuncSetAttribute(spatial_att2, cudaFuncAttributeMaxDynamicSharedMemorySize, SATT_SMEM);

    // 1) q,k projections (merged) and v projections
    qk_merged<<<dim3(NT/64, BATCH), 256>>>(t, tq_w, tq_b, tk_w, tk_b, q_t, k_t, NT);
    qk_merged<<<dim3(NS/64, BATCH), 256>>>(s, sq_w, sq_b, sk_w, sk_b, q_s, k_s, NS);
    gemm_bf16x3<64,false><<<dim3(NT/64, C/128, BATCH), 256, GSM_BYTES(64)>>>(tv_w, t, v_t, C, NT, C, 0, CNT, CNT, tv_b, nullptr, 0);
    gemm_bf16x3<128,false><<<dim3(NS/128, C/128, BATCH), 256, GSM_BYTES(128)>>>(sv_w, s, v_s, C, NS, C, 0, CNS, CNS, sv_b, nullptr, 0);

    // 2) spatial attention maps (softmax over batch axis) — fp32
    spatial_att2<<<dim3(NT/16, NT/16), 256, SATT_SMEM>>>(q_t, k_t, att_t, NT);
    spatial_att2<<<dim3(NS/16, NS/16), 256, SATT_SMEM>>>(q_s, k_s, att_s, NS);

    // 3) spatial out = v @ att
    gemm_bf16x3<64,false><<<dim3(NT/64, C/128, BATCH), 256, GSM_BYTES(64)>>>(v_t, att_t, at_, C, NT, NT, CNT, (long)NT*NT, CNT, nullptr, nullptr, 0);
    gemm_bf16x3<128,false><<<dim3(NS/128, C/128, BATCH), 256, GSM_BYTES(128)>>>(v_s, att_s, as_, C, NS, NS, CNS, (long)NS*NS, CNS, nullptr, nullptr, 0);

    // 4) grams G = f f^T (split-bf16 tensor; softmax gaps are huge -> safe), M = A_t + A_s
    gemm_bf16x3<64,true><<<dim3(C/64, C/128, BATCH), 256, GSM_BYTES(64)>>>(t, t, Gt, C, C, NT, CNT, CNT, CC, nullptr, nullptr, 0);
    gemm_bf16x3<64,true><<<dim3(C/64, C/128, BATCH), 256, GSM_BYTES(64)>>>(s, s, Gs, C, C, NS, CNS, CNS, CC, nullptr, nullptr, 0);
    softmax_col_add<<<dim3(C/32, BATCH), 256>>>(Gt, Mm, 0);
    softmax_col_add<<<dim3(C/32, BATCH), 256>>>(Gs, Mm, 1);

    // 5) at = (v@att) + t + M@t ; asr = (v@att) + s + M@s  (residual folded)
    gemm_bf16x3<64,false><<<dim3(NT/64, C/128, BATCH), 256, GSM_BYTES(64)>>>(Mm, t, at_, C, NT, C, CC, CNT, CNT, nullptr, t, 1);
    gemm_bf16x3<128,false><<<dim3(NS/128, C/128, BATCH), 256, GSM_BYTES(128)>>>(Mm, s, as_, C, NS, C, CC, CNS, CNS, nullptr, s, 1);

    // 6) offset/mask conv (27 channels)
    conv3x3_off<<<dim3(16, BATCH), 256>>>(at_, t_off_w, t_off_b, off_t, 16, 16);
    conv3x3_off<<<dim3(32, BATCH), 256>>>(as_, s_off_w, s_off_b, off_s, 32, 32);

    // 7) deformable bilinear sampling -> im2col
    dcn_sample<<<dim3(NT/64, 9, BATCH), 256>>>(at_, off_t, col_t, 16, 16);
    dcn_sample<<<dim3(NS/64, 9, BATCH), 256>>>(as_, off_s, col_s, 32, 32);

    // 8) dcn main GEMM: out = W(256x2304) @ col + bias
    gemm_bf16x3<64,false><<<dim3(NT/64, C/128, BATCH), 256, GSM_BYTES(64)>>>(t_dcn_w, col_t, out_t, C, NT, C*9, 0, (long)C*9*NT, CNT, t_dcn_b, nullptr, 0);
    gemm_bf16x3<128,false><<<dim3(NS/128, C/128, BATCH), 256, GSM_BYTES(128)>>>(s_dcn_w, col_s, out_s, C, NS, C*9, 0, (long)C*9*NS, CNS, s_dcn_b, nullptr, 0);
}